// round 11
// baseline (speedup 1.0000x reference)
#include <cuda_runtime.h>
#include <math.h>
#include <stdint.h>

#define BB 2
#define SS 2048
#define DD 1024
#define HH 16
#define HD 64
#define NTOK (BB * SS)

// Scratch (allocation-free rule: __device__ globals)
__device__ float g_Q[NTOK * DD];
__device__ float g_K[NTOK * DD];
__device__ float g_V[NTOK * DD];
__device__ float g_A[NTOK * DD];

__device__ __forceinline__ uint32_t f2tf32(float f) {
    uint32_t u;
    asm("cvt.rna.tf32.f32 %0, %1;" : "=r"(u) : "f"(f));
    return u;
}

// ---------------------------------------------------------------------------
// tf32 tensor-core GEMM:  C[M,N] = A[M,K] @ W[N,K]^T + bias[N]
// BM=128, BN=128, BK=32. 256 threads = 8 warps (4m x 2n), warp tile 32x64.
// mma.sync.aligned.m16n8k8.row.col.f32.tf32.tf32.f32
// ---------------------------------------------------------------------------
#define GBM 128
#define GBN 128
#define GBK 32

__global__ __launch_bounds__(256, 2) void gemm_tf32(
    const float* __restrict__ A, const float* __restrict__ W,
    const float* __restrict__ bias, float* __restrict__ C,
    int M, int N, int K)
{
    __shared__ float As[GBM][GBK + 4];
    __shared__ float Bs[GBN][GBK + 4];

    const int tid  = threadIdx.x;
    const int lane = tid & 31;
    const int warp = tid >> 5;
    const int g    = lane >> 2;   // groupID 0..7
    const int tg   = lane & 3;    // threadID_in_group 0..3
    const int wm   = warp >> 1;   // 0..3
    const int wn   = warp & 1;    // 0..1
    const int warpRow = wm * 32;
    const int warpCol = wn * 64;

    const int bm = blockIdx.y * GBM;
    const int bn = blockIdx.x * GBN;

    float acc[2][8][4];
#pragma unroll
    for (int i = 0; i < 2; i++)
#pragma unroll
        for (int j = 0; j < 8; j++)
#pragma unroll
            for (int r = 0; r < 4; r++) acc[i][j][r] = 0.f;

    const int f  = tid & 7;     // float4 col within 32-wide k slab
    const int r0 = tid >> 3;    // 0..31

    const float* Ag = A + (size_t)(bm + r0) * K + f * 4;
    const float* Wg = W + (size_t)(bn + r0) * K + f * 4;

    for (int k0 = 0; k0 < K; k0 += GBK) {
        __syncthreads();
#pragma unroll
        for (int i = 0; i < 4; i++) {
            float4 av = *(const float4*)(Ag + (size_t)(i * 32) * K + k0);
            float4 wv = *(const float4*)(Wg + (size_t)(i * 32) * K + k0);
            int rr = r0 + i * 32;
            As[rr][f * 4 + 0] = __uint_as_float(f2tf32(av.x));
            As[rr][f * 4 + 1] = __uint_as_float(f2tf32(av.y));
            As[rr][f * 4 + 2] = __uint_as_float(f2tf32(av.z));
            As[rr][f * 4 + 3] = __uint_as_float(f2tf32(av.w));
            Bs[rr][f * 4 + 0] = __uint_as_float(f2tf32(wv.x));
            Bs[rr][f * 4 + 1] = __uint_as_float(f2tf32(wv.y));
            Bs[rr][f * 4 + 2] = __uint_as_float(f2tf32(wv.z));
            Bs[rr][f * 4 + 3] = __uint_as_float(f2tf32(wv.w));
        }
        __syncthreads();

#pragma unroll
        for (int kk = 0; kk < 4; kk++) {
            const int kb = kk * 8;
            uint32_t a[2][4];
#pragma unroll
            for (int mf = 0; mf < 2; mf++) {
                const int r = warpRow + mf * 16 + g;
                a[mf][0] = __float_as_uint(As[r][kb + tg]);
                a[mf][1] = __float_as_uint(As[r + 8][kb + tg]);
                a[mf][2] = __float_as_uint(As[r][kb + tg + 4]);
                a[mf][3] = __float_as_uint(As[r + 8][kb + tg + 4]);
            }
            uint32_t b[8][2];
#pragma unroll
            for (int nf = 0; nf < 8; nf++) {
                const int c = warpCol + nf * 8 + g;
                b[nf][0] = __float_as_uint(Bs[c][kb + tg]);
                b[nf][1] = __float_as_uint(Bs[c][kb + tg + 4]);
            }
#pragma unroll
            for (int mf = 0; mf < 2; mf++)
#pragma unroll
                for (int nf = 0; nf < 8; nf++) {
                    asm volatile(
                        "mma.sync.aligned.m16n8k8.row.col.f32.tf32.tf32.f32 "
                        "{%0,%1,%2,%3}, {%4,%5,%6,%7}, {%8,%9}, {%0,%1,%2,%3};"
                        : "+f"(acc[mf][nf][0]), "+f"(acc[mf][nf][1]),
                          "+f"(acc[mf][nf][2]), "+f"(acc[mf][nf][3])
                        : "r"(a[mf][0]), "r"(a[mf][1]), "r"(a[mf][2]), "r"(a[mf][3]),
                          "r"(b[nf][0]), "r"(b[nf][1]));
                }
        }
    }

#pragma unroll
    for (int mf = 0; mf < 2; mf++) {
        const int r = bm + warpRow + mf * 16 + g;
#pragma unroll
        for (int nf = 0; nf < 8; nf++) {
            const int c = bn + warpCol + nf * 8 + 2 * tg;
            float2 bv = *(const float2*)&bias[c];
            float2 o0 = make_float2(acc[mf][nf][0] + bv.x, acc[mf][nf][1] + bv.y);
            float2 o1 = make_float2(acc[mf][nf][2] + bv.x, acc[mf][nf][3] + bv.y);
            *(float2*)&C[(size_t)r * N + c] = o0;
            *(float2*)&C[(size_t)(r + 8) * N + c] = o1;
        }
    }
}

// ---------------------------------------------------------------------------
// Causal ALiBi flash attention, v2.
// Block = 128 threads = 64 query rows x 2 half-threads. Each block processes
// TWO q-tiles (p and 31-p) so per-block work is constant (33 key-tiles).
// K/V tile in smem with +4-float offset between halves (bank-conflict-free).
// ---------------------------------------------------------------------------
#define KSTRIDE 72   // 32 | pad4 | 32 | pad4

__device__ __forceinline__ void attn_tile(
    int qt, int h, int b,
    const float* __restrict__ Q, const float* __restrict__ Kg,
    const float* __restrict__ Vg, float* __restrict__ O,
    float (*Ks)[KSTRIDE], float (*Vs)[KSTRIDE])
{
    const int t    = threadIdx.x;
    const int row  = t >> 1;
    const int half = t & 1;
    const int qrow = qt * 64 + row;
    const size_t base = ((size_t)b * SS) * DD + (size_t)h * HD;

    float q[32];
    {
        const float* qp = Q + base + (size_t)qrow * DD + half * 32;
#pragma unroll
        for (int d = 0; d < 32; d += 4) *(float4*)&q[d] = *(const float4*)(qp + d);
    }
    float o[32];
#pragma unroll
    for (int d = 0; d < 32; d++) o[d] = 0.f;

    float m = -1e30f, l = 0.f;
    const float slope = exp2f(-0.5f * (float)(h + 1));
    const float scale = 0.125f;
    const int hoff = half * 36;

    for (int kt = 0; kt <= qt; kt++) {
        __syncthreads();
        const float* kb = Kg + base + (size_t)(kt * 64) * DD;
        const float* vb = Vg + base + (size_t)(kt * 64) * DD;
#pragma unroll
        for (int i = 0; i < 8; i++) {
            int n = i * 128 + t;              // float4 index in 64x16 grid
            int r = n >> 4, c = (n & 15) << 2;
            int cs = c + (c >= 32 ? 4 : 0);   // padded dest col
            *(float4*)&Ks[r][cs] = *(const float4*)(kb + (size_t)r * DD + c);
            *(float4*)&Vs[r][cs] = *(const float4*)(vb + (size_t)r * DD + c);
        }
        __syncthreads();

        const bool diag = (kt == qt);

#pragma unroll 1
        for (int j0 = 0; j0 < 64; j0 += 16) {
            float s[16];
            float tmax = -1e30f;
#pragma unroll
            for (int jj = 0; jj < 16; jj++) {
                const int j = j0 + jj;
                const float* kr = &Ks[j][hoff];
                float a0 = 0.f, a1 = 0.f, a2 = 0.f, a3 = 0.f;
#pragma unroll
                for (int d = 0; d < 32; d += 4) {
                    float4 kv = *(const float4*)(kr + d);
                    a0 += q[d + 0] * kv.x;
                    a1 += q[d + 1] * kv.y;
                    a2 += q[d + 2] * kv.z;
                    a3 += q[d + 3] * kv.w;
                }
                float part = (a0 + a1) + (a2 + a3);
                part += __shfl_xor_sync(0xffffffffu, part, 1);
                const int kpos = kt * 64 + j;
                float sc = part * scale + slope * (float)(kpos - qrow);
                if (diag && kpos > qrow) sc = -1e30f;
                s[jj] = sc;
                tmax = fmaxf(tmax, sc);
            }
            const float mnew = fmaxf(m, tmax);
            const float alpha = __expf(m - mnew);
            float psum = 0.f;
#pragma unroll
            for (int jj = 0; jj < 16; jj++) {
                s[jj] = __expf(s[jj] - mnew);
                psum += s[jj];
            }
            l = l * alpha + psum;
            m = mnew;
#pragma unroll
            for (int d = 0; d < 32; d++) o[d] *= alpha;
#pragma unroll
            for (int jj = 0; jj < 16; jj++) {
                const float p = s[jj];
                const float* vr = &Vs[j0 + jj][hoff];
#pragma unroll
                for (int d = 0; d < 32; d += 4) {
                    float4 vv = *(const float4*)(vr + d);
                    o[d + 0] += p * vv.x;
                    o[d + 1] += p * vv.y;
                    o[d + 2] += p * vv.z;
                    o[d + 3] += p * vv.w;
                }
            }
        }
    }

    const float inv = 1.f / l;
    float* op = O + base + (size_t)qrow * DD + half * 32;
#pragma unroll
    for (int d = 0; d < 32; d += 4) {
        float4 ov = make_float4(o[d] * inv, o[d + 1] * inv,
                                o[d + 2] * inv, o[d + 3] * inv);
        *(float4*)(op + d) = ov;
    }
}

__global__ __launch_bounds__(128, 4) void attn_kernel2(
    const float* __restrict__ Q, const float* __restrict__ K,
    const float* __restrict__ V, float* __restrict__ O)
{
    __shared__ float Ks[64][KSTRIDE];
    __shared__ float Vs[64][KSTRIDE];
    const int p = blockIdx.x;   // 0..15
    const int h = blockIdx.y;
    const int b = blockIdx.z;
    attn_tile(p,      h, b, Q, K, V, O, Ks, Vs);
    attn_tile(31 - p, h, b, Q, K, V, O, Ks, Vs);
}

// ---------------------------------------------------------------------------
extern "C" void kernel_launch(void* const* d_in, const int* in_sizes, int n_in,
                              void* d_out, int out_size)
{
    (void)in_sizes; (void)n_in; (void)out_size;
    const float* x   = (const float*)d_in[0];
    const float* q_w = (const float*)d_in[1];
    const float* q_b = (const float*)d_in[2];
    const float* k_w = (const float*)d_in[3];
    const float* k_b = (const float*)d_in[4];
    const float* v_w = (const float*)d_in[5];
    const float* v_b = (const float*)d_in[6];
    const float* o_w = (const float*)d_in[7];
    const float* o_b = (const float*)d_in[8];
    float* out = (float*)d_out;

    float *Qp, *Kp, *Vp, *Ap;
    cudaGetSymbolAddress((void**)&Qp, g_Q);
    cudaGetSymbolAddress((void**)&Kp, g_K);
    cudaGetSymbolAddress((void**)&Vp, g_V);
    cudaGetSymbolAddress((void**)&Ap, g_A);

    dim3 gg(DD / GBN, NTOK / GBM);   // (8, 32)
    gemm_tf32<<<gg, 256>>>(x, q_w, q_b, Qp, NTOK, DD, DD);
    gemm_tf32<<<gg, 256>>>(x, k_w, k_b, Kp, NTOK, DD, DD);
    gemm_tf32<<<gg, 256>>>(x, v_w, v_b, Vp, NTOK, DD, DD);

    dim3 ga(SS / 128, HH, BB);       // (16, 16, 2)
    attn_kernel2<<<ga, 128>>>(Qp, Kp, Vp, Ap);

    gemm_tf32<<<gg, 256>>>(Ap, o_w, o_b, out, NTOK, DD, DD);
}

// round 12
// speedup vs baseline: 1.9829x; 1.9829x over previous
#include <cuda_runtime.h>
#include <math.h>
#include <stdint.h>

#define BB 2
#define SS 2048
#define DD 1024
#define HH 16
#define HD 64
#define NTOK (BB * SS)

// Scratch (allocation-free rule: __device__ globals)
__device__ float g_Q[NTOK * DD];
__device__ float g_K[NTOK * DD];
__device__ float g_V[NTOK * DD];
__device__ float g_A[NTOK * DD];

__device__ __forceinline__ uint32_t f2tf32(float f) {
    uint32_t u;
    asm("cvt.rna.tf32.f32 %0, %1;" : "=r"(u) : "f"(f));
    return u;
}

// ---------------------------------------------------------------------------
// tf32 tensor-core GEMM:  C[M,N] = A[M,K] @ W[N,K]^T + bias[N]
// BM=128, BN=128, BK=32. 256 threads = 8 warps (4m x 2n), warp tile 32x64.
// ---------------------------------------------------------------------------
#define GBM 128
#define GBN 128
#define GBK 32

__global__ __launch_bounds__(256, 2) void gemm_tf32(
    const float* __restrict__ A, const float* __restrict__ W,
    const float* __restrict__ bias, float* __restrict__ C,
    int M, int N, int K)
{
    __shared__ float As[GBM][GBK + 4];
    __shared__ float Bs[GBN][GBK + 4];

    const int tid  = threadIdx.x;
    const int lane = tid & 31;
    const int warp = tid >> 5;
    const int g    = lane >> 2;
    const int tg   = lane & 3;
    const int wm   = warp >> 1;
    const int wn   = warp & 1;
    const int warpRow = wm * 32;
    const int warpCol = wn * 64;

    const int bm = blockIdx.y * GBM;
    const int bn = blockIdx.x * GBN;

    float acc[2][8][4];
#pragma unroll
    for (int i = 0; i < 2; i++)
#pragma unroll
        for (int j = 0; j < 8; j++)
#pragma unroll
            for (int r = 0; r < 4; r++) acc[i][j][r] = 0.f;

    const int f  = tid & 7;
    const int r0 = tid >> 3;

    const float* Ag = A + (size_t)(bm + r0) * K + f * 4;
    const float* Wg = W + (size_t)(bn + r0) * K + f * 4;

    for (int k0 = 0; k0 < K; k0 += GBK) {
        __syncthreads();
#pragma unroll
        for (int i = 0; i < 4; i++) {
            float4 av = *(const float4*)(Ag + (size_t)(i * 32) * K + k0);
            float4 wv = *(const float4*)(Wg + (size_t)(i * 32) * K + k0);
            int rr = r0 + i * 32;
            As[rr][f * 4 + 0] = __uint_as_float(f2tf32(av.x));
            As[rr][f * 4 + 1] = __uint_as_float(f2tf32(av.y));
            As[rr][f * 4 + 2] = __uint_as_float(f2tf32(av.z));
            As[rr][f * 4 + 3] = __uint_as_float(f2tf32(av.w));
            Bs[rr][f * 4 + 0] = __uint_as_float(f2tf32(wv.x));
            Bs[rr][f * 4 + 1] = __uint_as_float(f2tf32(wv.y));
            Bs[rr][f * 4 + 2] = __uint_as_float(f2tf32(wv.z));
            Bs[rr][f * 4 + 3] = __uint_as_float(f2tf32(wv.w));
        }
        __syncthreads();

#pragma unroll
        for (int kk = 0; kk < 4; kk++) {
            const int kb = kk * 8;
            uint32_t a[2][4];
#pragma unroll
            for (int mf = 0; mf < 2; mf++) {
                const int r = warpRow + mf * 16 + g;
                a[mf][0] = __float_as_uint(As[r][kb + tg]);
                a[mf][1] = __float_as_uint(As[r + 8][kb + tg]);
                a[mf][2] = __float_as_uint(As[r][kb + tg + 4]);
                a[mf][3] = __float_as_uint(As[r + 8][kb + tg + 4]);
            }
            uint32_t b[8][2];
#pragma unroll
            for (int nf = 0; nf < 8; nf++) {
                const int c = warpCol + nf * 8 + g;
                b[nf][0] = __float_as_uint(Bs[c][kb + tg]);
                b[nf][1] = __float_as_uint(Bs[c][kb + tg + 4]);
            }
#pragma unroll
            for (int mf = 0; mf < 2; mf++)
#pragma unroll
                for (int nf = 0; nf < 8; nf++) {
                    asm volatile(
                        "mma.sync.aligned.m16n8k8.row.col.f32.tf32.tf32.f32 "
                        "{%0,%1,%2,%3}, {%4,%5,%6,%7}, {%8,%9}, {%0,%1,%2,%3};"
                        : "+f"(acc[mf][nf][0]), "+f"(acc[mf][nf][1]),
                          "+f"(acc[mf][nf][2]), "+f"(acc[mf][nf][3])
                        : "r"(a[mf][0]), "r"(a[mf][1]), "r"(a[mf][2]), "r"(a[mf][3]),
                          "r"(b[nf][0]), "r"(b[nf][1]));
                }
        }
    }

#pragma unroll
    for (int mf = 0; mf < 2; mf++) {
        const int r = bm + warpRow + mf * 16 + g;
#pragma unroll
        for (int nf = 0; nf < 8; nf++) {
            const int c = bn + warpCol + nf * 8 + 2 * tg;
            float2 bv = *(const float2*)&bias[c];
            float2 o0 = make_float2(acc[mf][nf][0] + bv.x, acc[mf][nf][1] + bv.y);
            float2 o1 = make_float2(acc[mf][nf][2] + bv.x, acc[mf][nf][3] + bv.y);
            *(float2*)&C[(size_t)r * N + c] = o0;
            *(float2*)&C[(size_t)(r + 8) * N + c] = o1;
        }
    }
}

// ---------------------------------------------------------------------------
// Tensor-core causal ALiBi flash attention (tf32 m16n8k8).
// Block = 128 threads = 4 warps; q-tile = 64 rows (16 per warp).
// Per key-tile: S = Q K^T (mma), register softmax, P -> smem (aliased on K
// tile), O += P V (mma). Blocks process q-tile pair (p, 31-p) for balance.
//
// smem strides chosen for conflict-free B-fragment reads:
//   K/P tile stride 68 (68 mod 32 == 4): bank = 4g + tg  -> 32 distinct
//   V tile stride 72 (72 mod 32 == 8): bank = 8tg + g    -> 32 distinct
// ---------------------------------------------------------------------------
#define KST 68
#define VST 72

__device__ __forceinline__ void attn_tile_mma(
    int qt, int h, int b,
    const float* __restrict__ Q, const float* __restrict__ Kg,
    const float* __restrict__ Vg, float* __restrict__ O,
    float (*KP)[KST], float (*Vs)[VST])
{
    const int tid  = threadIdx.x;
    const int lane = tid & 31;
    const int warp = tid >> 5;
    const int g    = lane >> 2;
    const int tg   = lane & 3;

    const size_t base = ((size_t)b * SS) * DD + (size_t)h * HD;
    const int qrow0 = qt * 64 + warp * 16 + g;      // row g of warp tile
    const int qrow1 = qrow0 + 8;                    // row g+8

    // Q fragments (scaled by 1/sqrt(hd), tf32)
    uint32_t qf[8][4];
    {
        const float* qp = Q + base + (size_t)qrow0 * DD;
        const float* qp8 = qp + 8 * DD;
#pragma unroll
        for (int kf = 0; kf < 8; kf++) {
            qf[kf][0] = f2tf32(qp [kf * 8 + tg]     * 0.125f);
            qf[kf][1] = f2tf32(qp8[kf * 8 + tg]     * 0.125f);
            qf[kf][2] = f2tf32(qp [kf * 8 + tg + 4] * 0.125f);
            qf[kf][3] = f2tf32(qp8[kf * 8 + tg + 4] * 0.125f);
        }
    }

    float o[8][4];
#pragma unroll
    for (int nf = 0; nf < 8; nf++)
#pragma unroll
        for (int r = 0; r < 4; r++) o[nf][r] = 0.f;

    float m0 = -1e30f, m1 = -1e30f, l0 = 0.f, l1 = 0.f;
    const float slope = exp2f(-0.5f * (float)(h + 1));

    float* pw = &KP[warp * 16][0];   // per-warp P region (aliases K tile)

    for (int kt = 0; kt <= qt; kt++) {
        __syncthreads();   // previous PV reads done; safe to refill KP/Vs
        {
            const float* kb = Kg + base + (size_t)(kt * 64) * DD;
            const float* vb = Vg + base + (size_t)(kt * 64) * DD;
#pragma unroll
            for (int i = 0; i < 8; i++) {
                int n = i * 128 + tid;
                int r = n >> 4, c = (n & 15) << 2;
                float4 kv = *(const float4*)(kb + (size_t)r * DD + c);
                float4 vv = *(const float4*)(vb + (size_t)r * DD + c);
                KP[r][c + 0] = __uint_as_float(f2tf32(kv.x));
                KP[r][c + 1] = __uint_as_float(f2tf32(kv.y));
                KP[r][c + 2] = __uint_as_float(f2tf32(kv.z));
                KP[r][c + 3] = __uint_as_float(f2tf32(kv.w));
                Vs[r][c + 0] = __uint_as_float(f2tf32(vv.x));
                Vs[r][c + 1] = __uint_as_float(f2tf32(vv.y));
                Vs[r][c + 2] = __uint_as_float(f2tf32(vv.z));
                Vs[r][c + 3] = __uint_as_float(f2tf32(vv.w));
            }
        }
        __syncthreads();   // tiles ready

        // ---- S = Q K^T ----
        float s[8][4];
#pragma unroll
        for (int nf = 0; nf < 8; nf++)
#pragma unroll
            for (int r = 0; r < 4; r++) s[nf][r] = 0.f;

#pragma unroll
        for (int kf = 0; kf < 8; kf++) {
            const int kb = kf * 8;
#pragma unroll
            for (int nf = 0; nf < 8; nf++) {
                uint32_t b0 = __float_as_uint(KP[nf * 8 + g][kb + tg]);
                uint32_t b1 = __float_as_uint(KP[nf * 8 + g][kb + tg + 4]);
                asm volatile(
                    "mma.sync.aligned.m16n8k8.row.col.f32.tf32.tf32.f32 "
                    "{%0,%1,%2,%3}, {%4,%5,%6,%7}, {%8,%9}, {%0,%1,%2,%3};"
                    : "+f"(s[nf][0]), "+f"(s[nf][1]), "+f"(s[nf][2]), "+f"(s[nf][3])
                    : "r"(qf[kf][0]), "r"(qf[kf][1]), "r"(qf[kf][2]), "r"(qf[kf][3]),
                      "r"(b0), "r"(b1));
            }
        }

        // ---- ALiBi bias (column-only; row term is softmax-invariant) + mask
        const bool diag = (kt == qt);
        const int colb = kt * 64 + 2 * tg;
#pragma unroll
        for (int nf = 0; nf < 8; nf++) {
            const int c0 = colb + nf * 8;
            const float b0f = slope * (float)c0;
            const float b1f = slope * (float)(c0 + 1);
            s[nf][0] += b0f; s[nf][1] += b1f;
            s[nf][2] += b0f; s[nf][3] += b1f;
            if (diag) {
                if (c0     > qrow0) s[nf][0] = -1e30f;
                if (c0 + 1 > qrow0) s[nf][1] = -1e30f;
                if (c0     > qrow1) s[nf][2] = -1e30f;
                if (c0 + 1 > qrow1) s[nf][3] = -1e30f;
            }
        }

        // ---- online softmax ----
        float mx0 = -1e30f, mx1 = -1e30f;
#pragma unroll
        for (int nf = 0; nf < 8; nf++) {
            mx0 = fmaxf(mx0, fmaxf(s[nf][0], s[nf][1]));
            mx1 = fmaxf(mx1, fmaxf(s[nf][2], s[nf][3]));
        }
        mx0 = fmaxf(mx0, __shfl_xor_sync(0xffffffffu, mx0, 1));
        mx0 = fmaxf(mx0, __shfl_xor_sync(0xffffffffu, mx0, 2));
        mx1 = fmaxf(mx1, __shfl_xor_sync(0xffffffffu, mx1, 1));
        mx1 = fmaxf(mx1, __shfl_xor_sync(0xffffffffu, mx1, 2));

        const float mn0 = fmaxf(m0, mx0);
        const float mn1 = fmaxf(m1, mx1);
        const float a0 = __expf(m0 - mn0);
        const float a1 = __expf(m1 - mn1);
        m0 = mn0; m1 = mn1;

        float sum0 = 0.f, sum1 = 0.f;
#pragma unroll
        for (int nf = 0; nf < 8; nf++) {
            s[nf][0] = __expf(s[nf][0] - mn0);
            s[nf][1] = __expf(s[nf][1] - mn0);
            s[nf][2] = __expf(s[nf][2] - mn1);
            s[nf][3] = __expf(s[nf][3] - mn1);
            sum0 += s[nf][0] + s[nf][1];
            sum1 += s[nf][2] + s[nf][3];
        }
        sum0 += __shfl_xor_sync(0xffffffffu, sum0, 1);
        sum0 += __shfl_xor_sync(0xffffffffu, sum0, 2);
        sum1 += __shfl_xor_sync(0xffffffffu, sum1, 1);
        sum1 += __shfl_xor_sync(0xffffffffu, sum1, 2);
        l0 = l0 * a0 + sum0;
        l1 = l1 * a1 + sum1;

#pragma unroll
        for (int nf = 0; nf < 8; nf++) {
            o[nf][0] *= a0; o[nf][1] *= a0;
            o[nf][2] *= a1; o[nf][3] *= a1;
        }

        __syncthreads();   // all warps finished reading K tile from KP

        // ---- P -> per-warp smem region (tf32) ----
#pragma unroll
        for (int nf = 0; nf < 8; nf++) {
            float2 p0 = make_float2(__uint_as_float(f2tf32(s[nf][0])),
                                    __uint_as_float(f2tf32(s[nf][1])));
            float2 p1 = make_float2(__uint_as_float(f2tf32(s[nf][2])),
                                    __uint_as_float(f2tf32(s[nf][3])));
            *(float2*)&pw[(size_t)g * KST + nf * 8 + 2 * tg]       = p0;
            *(float2*)&pw[(size_t)(g + 8) * KST + nf * 8 + 2 * tg] = p1;
        }
        __syncwarp();

        // ---- O += P V ----
#pragma unroll
        for (int kf = 0; kf < 8; kf++) {
            const int kb = kf * 8;
            uint32_t pa[4];
            pa[0] = __float_as_uint(pw[(size_t)g * KST + kb + tg]);
            pa[1] = __float_as_uint(pw[(size_t)(g + 8) * KST + kb + tg]);
            pa[2] = __float_as_uint(pw[(size_t)g * KST + kb + tg + 4]);
            pa[3] = __float_as_uint(pw[(size_t)(g + 8) * KST + kb + tg + 4]);
#pragma unroll
            for (int nf = 0; nf < 8; nf++) {
                uint32_t b0 = __float_as_uint(Vs[kb + tg][nf * 8 + g]);
                uint32_t b1 = __float_as_uint(Vs[kb + tg + 4][nf * 8 + g]);
                asm volatile(
                    "mma.sync.aligned.m16n8k8.row.col.f32.tf32.tf32.f32 "
                    "{%0,%1,%2,%3}, {%4,%5,%6,%7}, {%8,%9}, {%0,%1,%2,%3};"
                    : "+f"(o[nf][0]), "+f"(o[nf][1]), "+f"(o[nf][2]), "+f"(o[nf][3])
                    : "r"(pa[0]), "r"(pa[1]), "r"(pa[2]), "r"(pa[3]),
                      "r"(b0), "r"(b1));
            }
        }
    }

    // ---- normalize + write ----
    const float i0 = 1.f / l0;
    const float i1 = 1.f / l1;
    float* op0 = O + base + (size_t)qrow0 * DD;
    float* op1 = O + base + (size_t)qrow1 * DD;
#pragma unroll
    for (int nf = 0; nf < 8; nf++) {
        const int c = nf * 8 + 2 * tg;
        *(float2*)&op0[c] = make_float2(o[nf][0] * i0, o[nf][1] * i0);
        *(float2*)&op1[c] = make_float2(o[nf][2] * i1, o[nf][3] * i1);
    }
}

__global__ __launch_bounds__(128, 3) void attn_mma_kernel(
    const float* __restrict__ Q, const float* __restrict__ K,
    const float* __restrict__ V, float* __restrict__ O)
{
    __shared__ float KP[64][KST];
    __shared__ float Vs[64][VST];
    const int p = blockIdx.x;   // 0..15
    const int h = blockIdx.y;
    const int b = blockIdx.z;
    attn_tile_mma(p,      h, b, Q, K, V, O, KP, Vs);
    attn_tile_mma(31 - p, h, b, Q, K, V, O, KP, Vs);
}

// ---------------------------------------------------------------------------
extern "C" void kernel_launch(void* const* d_in, const int* in_sizes, int n_in,
                              void* d_out, int out_size)
{
    (void)in_sizes; (void)n_in; (void)out_size;
    const float* x   = (const float*)d_in[0];
    const float* q_w = (const float*)d_in[1];
    const float* q_b = (const float*)d_in[2];
    const float* k_w = (const float*)d_in[3];
    const float* k_b = (const float*)d_in[4];
    const float* v_w = (const float*)d_in[5];
    const float* v_b = (const float*)d_in[6];
    const float* o_w = (const float*)d_in[7];
    const float* o_b = (const float*)d_in[8];
    float* out = (float*)d_out;

    float *Qp, *Kp, *Vp, *Ap;
    cudaGetSymbolAddress((void**)&Qp, g_Q);
    cudaGetSymbolAddress((void**)&Kp, g_K);
    cudaGetSymbolAddress((void**)&Vp, g_V);
    cudaGetSymbolAddress((void**)&Ap, g_A);

    dim3 gg(DD / GBN, NTOK / GBM);   // (8, 32)
    gemm_tf32<<<gg, 256>>>(x, q_w, q_b, Qp, NTOK, DD, DD);
    gemm_tf32<<<gg, 256>>>(x, k_w, k_b, Kp, NTOK, DD, DD);
    gemm_tf32<<<gg, 256>>>(x, v_w, v_b, Vp, NTOK, DD, DD);

    dim3 ga(SS / 128, HH, BB);       // (16, 16, 2)
    attn_mma_kernel<<<ga, 128>>>(Qp, Kp, Vp, Ap);

    gemm_tf32<<<gg, 256>>>(Ap, o_w, o_b, out, NTOK, DD, DD);
}

// round 13
// speedup vs baseline: 1.9911x; 1.0041x over previous
#include <cuda_runtime.h>
#include <math.h>
#include <stdint.h>

#define BB 2
#define SS 2048
#define DD 1024
#define HH 16
#define HD 64
#define NTOK (BB * SS)

// Scratch (allocation-free rule: __device__ globals)
__device__ float g_Q[NTOK * DD];
__device__ float g_K[NTOK * DD];
__device__ float g_V[NTOK * DD];
__device__ float g_A[NTOK * DD];

__device__ __forceinline__ uint32_t f2tf32(float f) {
    uint32_t u;
    asm("cvt.rna.tf32.f32 %0, %1;" : "=r"(u) : "f"(f));
    return u;
}

// ---------------------------------------------------------------------------
// tf32 tensor-core GEMM:  C[M,N] = A[M,K] @ W[N,K]^T + bias[N]
// BM=128, BN=128, BK=32. 256 threads = 8 warps (4m x 2n), warp tile 32x64.
// ---------------------------------------------------------------------------
#define GBM 128
#define GBN 128
#define GBK 32

__global__ __launch_bounds__(256, 2) void gemm_tf32(
    const float* __restrict__ A, const float* __restrict__ W,
    const float* __restrict__ bias, float* __restrict__ C,
    int M, int N, int K)
{
    __shared__ float As[GBM][GBK + 4];
    __shared__ float Bs[GBN][GBK + 4];

    const int tid  = threadIdx.x;
    const int lane = tid & 31;
    const int warp = tid >> 5;
    const int g    = lane >> 2;
    const int tg   = lane & 3;
    const int wm   = warp >> 1;
    const int wn   = warp & 1;
    const int warpRow = wm * 32;
    const int warpCol = wn * 64;

    const int bm = blockIdx.y * GBM;
    const int bn = blockIdx.x * GBN;

    float acc[2][8][4];
#pragma unroll
    for (int i = 0; i < 2; i++)
#pragma unroll
        for (int j = 0; j < 8; j++)
#pragma unroll
            for (int r = 0; r < 4; r++) acc[i][j][r] = 0.f;

    const int f  = tid & 7;
    const int r0 = tid >> 3;

    const float* Ag = A + (size_t)(bm + r0) * K + f * 4;
    const float* Wg = W + (size_t)(bn + r0) * K + f * 4;

    for (int k0 = 0; k0 < K; k0 += GBK) {
        __syncthreads();
#pragma unroll
        for (int i = 0; i < 4; i++) {
            float4 av = *(const float4*)(Ag + (size_t)(i * 32) * K + k0);
            float4 wv = *(const float4*)(Wg + (size_t)(i * 32) * K + k0);
            int rr = r0 + i * 32;
            As[rr][f * 4 + 0] = __uint_as_float(f2tf32(av.x));
            As[rr][f * 4 + 1] = __uint_as_float(f2tf32(av.y));
            As[rr][f * 4 + 2] = __uint_as_float(f2tf32(av.z));
            As[rr][f * 4 + 3] = __uint_as_float(f2tf32(av.w));
            Bs[rr][f * 4 + 0] = __uint_as_float(f2tf32(wv.x));
            Bs[rr][f * 4 + 1] = __uint_as_float(f2tf32(wv.y));
            Bs[rr][f * 4 + 2] = __uint_as_float(f2tf32(wv.z));
            Bs[rr][f * 4 + 3] = __uint_as_float(f2tf32(wv.w));
        }
        __syncthreads();

#pragma unroll
        for (int kk = 0; kk < 4; kk++) {
            const int kb = kk * 8;
            uint32_t a[2][4];
#pragma unroll
            for (int mf = 0; mf < 2; mf++) {
                const int r = warpRow + mf * 16 + g;
                a[mf][0] = __float_as_uint(As[r][kb + tg]);
                a[mf][1] = __float_as_uint(As[r + 8][kb + tg]);
                a[mf][2] = __float_as_uint(As[r][kb + tg + 4]);
                a[mf][3] = __float_as_uint(As[r + 8][kb + tg + 4]);
            }
            uint32_t b[8][2];
#pragma unroll
            for (int nf = 0; nf < 8; nf++) {
                const int c = warpCol + nf * 8 + g;
                b[nf][0] = __float_as_uint(Bs[c][kb + tg]);
                b[nf][1] = __float_as_uint(Bs[c][kb + tg + 4]);
            }
#pragma unroll
            for (int mf = 0; mf < 2; mf++)
#pragma unroll
                for (int nf = 0; nf < 8; nf++) {
                    asm volatile(
                        "mma.sync.aligned.m16n8k8.row.col.f32.tf32.tf32.f32 "
                        "{%0,%1,%2,%3}, {%4,%5,%6,%7}, {%8,%9}, {%0,%1,%2,%3};"
                        : "+f"(acc[mf][nf][0]), "+f"(acc[mf][nf][1]),
                          "+f"(acc[mf][nf][2]), "+f"(acc[mf][nf][3])
                        : "r"(a[mf][0]), "r"(a[mf][1]), "r"(a[mf][2]), "r"(a[mf][3]),
                          "r"(b[nf][0]), "r"(b[nf][1]));
                }
        }
    }

#pragma unroll
    for (int mf = 0; mf < 2; mf++) {
        const int r = bm + warpRow + mf * 16 + g;
#pragma unroll
        for (int nf = 0; nf < 8; nf++) {
            const int c = bn + warpCol + nf * 8 + 2 * tg;
            float2 bv = *(const float2*)&bias[c];
            float2 o0 = make_float2(acc[mf][nf][0] + bv.x, acc[mf][nf][1] + bv.y);
            float2 o1 = make_float2(acc[mf][nf][2] + bv.x, acc[mf][nf][3] + bv.y);
            *(float2*)&C[(size_t)r * N + c] = o0;
            *(float2*)&C[(size_t)(r + 8) * N + c] = o1;
        }
    }
}

// ---------------------------------------------------------------------------
// Tensor-core causal ALiBi flash attention (tf32 m16n8k8).
// Block = 128 threads = 4 warps; q-tile = 64 rows (16 per warp).
// Per key-tile: S = Q K^T (mma), register softmax, P -> smem (aliased on K
// tile), O += P V (mma). Blocks process q-tile pair (p, 31-p) for balance.
//
// smem strides chosen for conflict-free B-fragment reads:
//   K/P tile stride 68 (68 mod 32 == 4): bank = 4g + tg  -> 32 distinct
//   V tile stride 72 (72 mod 32 == 8): bank = 8tg + g    -> 32 distinct
// ---------------------------------------------------------------------------
#define KST 68
#define VST 72

__device__ __forceinline__ void attn_tile_mma(
    int qt, int h, int b,
    const float* __restrict__ Q, const float* __restrict__ Kg,
    const float* __restrict__ Vg, float* __restrict__ O,
    float (*KP)[KST], float (*Vs)[VST])
{
    const int tid  = threadIdx.x;
    const int lane = tid & 31;
    const int warp = tid >> 5;
    const int g    = lane >> 2;
    const int tg   = lane & 3;

    const size_t base = ((size_t)b * SS) * DD + (size_t)h * HD;
    const int qrow0 = qt * 64 + warp * 16 + g;      // row g of warp tile
    const int qrow1 = qrow0 + 8;                    // row g+8

    // Q fragments (scaled by 1/sqrt(hd), tf32)
    uint32_t qf[8][4];
    {
        const float* qp = Q + base + (size_t)qrow0 * DD;
        const float* qp8 = qp + 8 * DD;
#pragma unroll
        for (int kf = 0; kf < 8; kf++) {
            qf[kf][0] = f2tf32(qp [kf * 8 + tg]     * 0.125f);
            qf[kf][1] = f2tf32(qp8[kf * 8 + tg]     * 0.125f);
            qf[kf][2] = f2tf32(qp [kf * 8 + tg + 4] * 0.125f);
            qf[kf][3] = f2tf32(qp8[kf * 8 + tg + 4] * 0.125f);
        }
    }

    float o[8][4];
#pragma unroll
    for (int nf = 0; nf < 8; nf++)
#pragma unroll
        for (int r = 0; r < 4; r++) o[nf][r] = 0.f;

    float m0 = -1e30f, m1 = -1e30f, l0 = 0.f, l1 = 0.f;
    const float slope = exp2f(-0.5f * (float)(h + 1));

    float* pw = &KP[warp * 16][0];   // per-warp P region (aliases K tile)

    for (int kt = 0; kt <= qt; kt++) {
        __syncthreads();   // previous PV reads done; safe to refill KP/Vs
        {
            const float* kb = Kg + base + (size_t)(kt * 64) * DD;
            const float* vb = Vg + base + (size_t)(kt * 64) * DD;
#pragma unroll
            for (int i = 0; i < 8; i++) {
                int n = i * 128 + tid;
                int r = n >> 4, c = (n & 15) << 2;
                float4 kv = *(const float4*)(kb + (size_t)r * DD + c);
                float4 vv = *(const float4*)(vb + (size_t)r * DD + c);
                KP[r][c + 0] = __uint_as_float(f2tf32(kv.x));
                KP[r][c + 1] = __uint_as_float(f2tf32(kv.y));
                KP[r][c + 2] = __uint_as_float(f2tf32(kv.z));
                KP[r][c + 3] = __uint_as_float(f2tf32(kv.w));
                Vs[r][c + 0] = __uint_as_float(f2tf32(vv.x));
                Vs[r][c + 1] = __uint_as_float(f2tf32(vv.y));
                Vs[r][c + 2] = __uint_as_float(f2tf32(vv.z));
                Vs[r][c + 3] = __uint_as_float(f2tf32(vv.w));
            }
        }
        __syncthreads();   // tiles ready

        // ---- S = Q K^T ----
        float s[8][4];
#pragma unroll
        for (int nf = 0; nf < 8; nf++)
#pragma unroll
            for (int r = 0; r < 4; r++) s[nf][r] = 0.f;

#pragma unroll
        for (int kf = 0; kf < 8; kf++) {
            const int kb = kf * 8;
#pragma unroll
            for (int nf = 0; nf < 8; nf++) {
                uint32_t b0 = __float_as_uint(KP[nf * 8 + g][kb + tg]);
                uint32_t b1 = __float_as_uint(KP[nf * 8 + g][kb + tg + 4]);
                asm volatile(
                    "mma.sync.aligned.m16n8k8.row.col.f32.tf32.tf32.f32 "
                    "{%0,%1,%2,%3}, {%4,%5,%6,%7}, {%8,%9}, {%0,%1,%2,%3};"
                    : "+f"(s[nf][0]), "+f"(s[nf][1]), "+f"(s[nf][2]), "+f"(s[nf][3])
                    : "r"(qf[kf][0]), "r"(qf[kf][1]), "r"(qf[kf][2]), "r"(qf[kf][3]),
                      "r"(b0), "r"(b1));
            }
        }

        // ---- ALiBi bias (column-only; row term is softmax-invariant) + mask
        const bool diag = (kt == qt);
        const int colb = kt * 64 + 2 * tg;
#pragma unroll
        for (int nf = 0; nf < 8; nf++) {
            const int c0 = colb + nf * 8;
            const float b0f = slope * (float)c0;
            const float b1f = slope * (float)(c0 + 1);
            s[nf][0] += b0f; s[nf][1] += b1f;
            s[nf][2] += b0f; s[nf][3] += b1f;
            if (diag) {
                if (c0     > qrow0) s[nf][0] = -1e30f;
                if (c0 + 1 > qrow0) s[nf][1] = -1e30f;
                if (c0     > qrow1) s[nf][2] = -1e30f;
                if (c0 + 1 > qrow1) s[nf][3] = -1e30f;
            }
        }

        // ---- online softmax ----
        float mx0 = -1e30f, mx1 = -1e30f;
#pragma unroll
        for (int nf = 0; nf < 8; nf++) {
            mx0 = fmaxf(mx0, fmaxf(s[nf][0], s[nf][1]));
            mx1 = fmaxf(mx1, fmaxf(s[nf][2], s[nf][3]));
        }
        mx0 = fmaxf(mx0, __shfl_xor_sync(0xffffffffu, mx0, 1));
        mx0 = fmaxf(mx0, __shfl_xor_sync(0xffffffffu, mx0, 2));
        mx1 = fmaxf(mx1, __shfl_xor_sync(0xffffffffu, mx1, 1));
        mx1 = fmaxf(mx1, __shfl_xor_sync(0xffffffffu, mx1, 2));

        const float mn0 = fmaxf(m0, mx0);
        const float mn1 = fmaxf(m1, mx1);
        const float a0 = __expf(m0 - mn0);
        const float a1 = __expf(m1 - mn1);
        m0 = mn0; m1 = mn1;

        float sum0 = 0.f, sum1 = 0.f;
#pragma unroll
        for (int nf = 0; nf < 8; nf++) {
            s[nf][0] = __expf(s[nf][0] - mn0);
            s[nf][1] = __expf(s[nf][1] - mn0);
            s[nf][2] = __expf(s[nf][2] - mn1);
            s[nf][3] = __expf(s[nf][3] - mn1);
            sum0 += s[nf][0] + s[nf][1];
            sum1 += s[nf][2] + s[nf][3];
        }
        sum0 += __shfl_xor_sync(0xffffffffu, sum0, 1);
        sum0 += __shfl_xor_sync(0xffffffffu, sum0, 2);
        sum1 += __shfl_xor_sync(0xffffffffu, sum1, 1);
        sum1 += __shfl_xor_sync(0xffffffffu, sum1, 2);
        l0 = l0 * a0 + sum0;
        l1 = l1 * a1 + sum1;

#pragma unroll
        for (int nf = 0; nf < 8; nf++) {
            o[nf][0] *= a0; o[nf][1] *= a0;
            o[nf][2] *= a1; o[nf][3] *= a1;
        }

        __syncthreads();   // all warps finished reading K tile from KP

        // ---- P -> per-warp smem region (tf32) ----
#pragma unroll
        for (int nf = 0; nf < 8; nf++) {
            float2 p0 = make_float2(__uint_as_float(f2tf32(s[nf][0])),
                                    __uint_as_float(f2tf32(s[nf][1])));
            float2 p1 = make_float2(__uint_as_float(f2tf32(s[nf][2])),
                                    __uint_as_float(f2tf32(s[nf][3])));
            *(float2*)&pw[(size_t)g * KST + nf * 8 + 2 * tg]       = p0;
            *(float2*)&pw[(size_t)(g + 8) * KST + nf * 8 + 2 * tg] = p1;
        }
        __syncwarp();

        // ---- O += P V ----
#pragma unroll
        for (int kf = 0; kf < 8; kf++) {
            const int kb = kf * 8;
            uint32_t pa[4];
            pa[0] = __float_as_uint(pw[(size_t)g * KST + kb + tg]);
            pa[1] = __float_as_uint(pw[(size_t)(g + 8) * KST + kb + tg]);
            pa[2] = __float_as_uint(pw[(size_t)g * KST + kb + tg + 4]);
            pa[3] = __float_as_uint(pw[(size_t)(g + 8) * KST + kb + tg + 4]);
#pragma unroll
            for (int nf = 0; nf < 8; nf++) {
                uint32_t b0 = __float_as_uint(Vs[kb + tg][nf * 8 + g]);
                uint32_t b1 = __float_as_uint(Vs[kb + tg + 4][nf * 8 + g]);
                asm volatile(
                    "mma.sync.aligned.m16n8k8.row.col.f32.tf32.tf32.f32 "
                    "{%0,%1,%2,%3}, {%4,%5,%6,%7}, {%8,%9}, {%0,%1,%2,%3};"
                    : "+f"(o[nf][0]), "+f"(o[nf][1]), "+f"(o[nf][2]), "+f"(o[nf][3])
                    : "r"(pa[0]), "r"(pa[1]), "r"(pa[2]), "r"(pa[3]),
                      "r"(b0), "r"(b1));
            }
        }
    }

    // ---- normalize + write ----
    const float i0 = 1.f / l0;
    const float i1 = 1.f / l1;
    float* op0 = O + base + (size_t)qrow0 * DD;
    float* op1 = O + base + (size_t)qrow1 * DD;
#pragma unroll
    for (int nf = 0; nf < 8; nf++) {
        const int c = nf * 8 + 2 * tg;
        *(float2*)&op0[c] = make_float2(o[nf][0] * i0, o[nf][1] * i0);
        *(float2*)&op1[c] = make_float2(o[nf][2] * i1, o[nf][3] * i1);
    }
}

__global__ __launch_bounds__(128, 3) void attn_mma_kernel(
    const float* __restrict__ Q, const float* __restrict__ K,
    const float* __restrict__ V, float* __restrict__ O)
{
    __shared__ float KP[64][KST];
    __shared__ float Vs[64][VST];
    const int p = blockIdx.x;   // 0..15
    const int h = blockIdx.y;
    const int b = blockIdx.z;
    attn_tile_mma(p,      h, b, Q, K, V, O, KP, Vs);
    attn_tile_mma(31 - p, h, b, Q, K, V, O, KP, Vs);
}

// ---------------------------------------------------------------------------
extern "C" void kernel_launch(void* const* d_in, const int* in_sizes, int n_in,
                              void* d_out, int out_size)
{
    (void)in_sizes; (void)n_in; (void)out_size;
    const float* x   = (const float*)d_in[0];
    const float* q_w = (const float*)d_in[1];
    const float* q_b = (const float*)d_in[2];
    const float* k_w = (const float*)d_in[3];
    const float* k_b = (const float*)d_in[4];
    const float* v_w = (const float*)d_in[5];
    const float* v_b = (const float*)d_in[6];
    const float* o_w = (const float*)d_in[7];
    const float* o_b = (const float*)d_in[8];
    float* out = (float*)d_out;

    float *Qp, *Kp, *Vp, *Ap;
    cudaGetSymbolAddress((void**)&Qp, g_Q);
    cudaGetSymbolAddress((void**)&Kp, g_K);
    cudaGetSymbolAddress((void**)&Vp, g_V);
    cudaGetSymbolAddress((void**)&Ap, g_A);

    dim3 gg(DD / GBN, NTOK / GBM);   // (8, 32)
    gemm_tf32<<<gg, 256>>>(x, q_w, q_b, Qp, NTOK, DD, DD);
    gemm_tf32<<<gg, 256>>>(x, k_w, k_b, Kp, NTOK, DD, DD);
    gemm_tf32<<<gg, 256>>>(x, v_w, v_b, Vp, NTOK, DD, DD);

    dim3 ga(SS / 128, HH, BB);       // (16, 16, 2)
    attn_mma_kernel<<<ga, 128>>>(Qp, Kp, Vp, Ap);

    gemm_tf32<<<gg, 256>>>(Ap, o_w, o_b, out, NTOK, DD, DD);
}

// round 14
// speedup vs baseline: 2.2101x; 1.1100x over previous
#include <cuda_runtime.h>
#include <math.h>
#include <stdint.h>

#define BB 2
#define SS 2048
#define DD 1024
#define HH 16
#define HD 64
#define NTOK (BB * SS)

// Scratch (allocation-free rule: __device__ globals)
__device__ float g_Q[NTOK * DD];
__device__ float g_K[NTOK * DD];
__device__ float g_V[NTOK * DD];
__device__ float g_A[NTOK * DD];

__device__ __forceinline__ uint32_t f2tf32(float f) {
    uint32_t u;
    asm("cvt.rna.tf32.f32 %0, %1;" : "=r"(u) : "f"(f));
    return u;
}

// ---------------------------------------------------------------------------
// tf32 tensor-core GEMM:  C[M,N] = A[M,K] @ W[N,K]^T + bias[N]
// BM=128, BN=128, BK=32. 256 threads = 8 warps (4m x 2n), warp tile 32x64.
// Register prefetch of the next k-slab hides LDG latency behind the mma work.
// ---------------------------------------------------------------------------
#define GBM 128
#define GBN 128
#define GBK 32

__global__ __launch_bounds__(256, 2) void gemm_tf32(
    const float* __restrict__ A, const float* __restrict__ W,
    const float* __restrict__ bias, float* __restrict__ C,
    int M, int N, int K)
{
    __shared__ float As[GBM][GBK + 4];
    __shared__ float Bs[GBN][GBK + 4];

    const int tid  = threadIdx.x;
    const int lane = tid & 31;
    const int warp = tid >> 5;
    const int g    = lane >> 2;
    const int tg   = lane & 3;
    const int wm   = warp >> 1;
    const int wn   = warp & 1;
    const int warpRow = wm * 32;
    const int warpCol = wn * 64;

    const int bm = blockIdx.y * GBM;
    const int bn = blockIdx.x * GBN;

    float acc[2][8][4];
#pragma unroll
    for (int i = 0; i < 2; i++)
#pragma unroll
        for (int j = 0; j < 8; j++)
#pragma unroll
            for (int r = 0; r < 4; r++) acc[i][j][r] = 0.f;

    const int f  = tid & 7;
    const int r0 = tid >> 3;

    const float* Ag = A + (size_t)(bm + r0) * K + f * 4;
    const float* Wg = W + (size_t)(bn + r0) * K + f * 4;

    float4 avp[4], wvp[4];
#pragma unroll
    for (int i = 0; i < 4; i++) {
        avp[i] = *(const float4*)(Ag + (size_t)(i * 32) * K);
        wvp[i] = *(const float4*)(Wg + (size_t)(i * 32) * K);
    }

    for (int k0 = 0; k0 < K; k0 += GBK) {
        __syncthreads();   // previous compute done
#pragma unroll
        for (int i = 0; i < 4; i++) {
            int rr = r0 + i * 32;
            As[rr][f * 4 + 0] = __uint_as_float(f2tf32(avp[i].x));
            As[rr][f * 4 + 1] = __uint_as_float(f2tf32(avp[i].y));
            As[rr][f * 4 + 2] = __uint_as_float(f2tf32(avp[i].z));
            As[rr][f * 4 + 3] = __uint_as_float(f2tf32(avp[i].w));
            Bs[rr][f * 4 + 0] = __uint_as_float(f2tf32(wvp[i].x));
            Bs[rr][f * 4 + 1] = __uint_as_float(f2tf32(wvp[i].y));
            Bs[rr][f * 4 + 2] = __uint_as_float(f2tf32(wvp[i].z));
            Bs[rr][f * 4 + 3] = __uint_as_float(f2tf32(wvp[i].w));
        }
        __syncthreads();

        if (k0 + GBK < K) {
#pragma unroll
            for (int i = 0; i < 4; i++) {
                avp[i] = *(const float4*)(Ag + (size_t)(i * 32) * K + k0 + GBK);
                wvp[i] = *(const float4*)(Wg + (size_t)(i * 32) * K + k0 + GBK);
            }
        }

#pragma unroll
        for (int kk = 0; kk < 4; kk++) {
            const int kb = kk * 8;
            uint32_t a[2][4];
#pragma unroll
            for (int mf = 0; mf < 2; mf++) {
                const int r = warpRow + mf * 16 + g;
                a[mf][0] = __float_as_uint(As[r][kb + tg]);
                a[mf][1] = __float_as_uint(As[r + 8][kb + tg]);
                a[mf][2] = __float_as_uint(As[r][kb + tg + 4]);
                a[mf][3] = __float_as_uint(As[r + 8][kb + tg + 4]);
            }
            uint32_t b[8][2];
#pragma unroll
            for (int nf = 0; nf < 8; nf++) {
                const int c = warpCol + nf * 8 + g;
                b[nf][0] = __float_as_uint(Bs[c][kb + tg]);
                b[nf][1] = __float_as_uint(Bs[c][kb + tg + 4]);
            }
#pragma unroll
            for (int mf = 0; mf < 2; mf++)
#pragma unroll
                for (int nf = 0; nf < 8; nf++) {
                    asm volatile(
                        "mma.sync.aligned.m16n8k8.row.col.f32.tf32.tf32.f32 "
                        "{%0,%1,%2,%3}, {%4,%5,%6,%7}, {%8,%9}, {%0,%1,%2,%3};"
                        : "+f"(acc[mf][nf][0]), "+f"(acc[mf][nf][1]),
                          "+f"(acc[mf][nf][2]), "+f"(acc[mf][nf][3])
                        : "r"(a[mf][0]), "r"(a[mf][1]), "r"(a[mf][2]), "r"(a[mf][3]),
                          "r"(b[nf][0]), "r"(b[nf][1]));
                }
        }
    }

#pragma unroll
    for (int mf = 0; mf < 2; mf++) {
        const int r = bm + warpRow + mf * 16 + g;
#pragma unroll
        for (int nf = 0; nf < 8; nf++) {
            const int c = bn + warpCol + nf * 8 + 2 * tg;
            float2 bv = *(const float2*)&bias[c];
            float2 o0 = make_float2(acc[mf][nf][0] + bv.x, acc[mf][nf][1] + bv.y);
            float2 o1 = make_float2(acc[mf][nf][2] + bv.x, acc[mf][nf][3] + bv.y);
            *(float2*)&C[(size_t)r * N + c] = o0;
            *(float2*)&C[(size_t)(r + 8) * N + c] = o1;
        }
    }
}

// ---------------------------------------------------------------------------
// Tensor-core causal ALiBi flash attention (tf32 m16n8k8), P-in-registers.
//
// The S output fragment (cols {2tg, 2tg+1}) is reused directly as the PV
// A-fragment by permuting the key axis of V's B-fragment reads:
//   k-slot kappa -> V row 8*kf + f(kappa), f = [0,2,4,6,1,3,5,7]
// so pa = (s[kf][0], s[kf][2], s[kf][1], s[kf][3]) with no shuffles/smem.
//
// Bank math: KST=68 (68%32=4): K b-frags bank 4g+tg -> conflict-free.
//            VST=68: V b-frag rows {8kf+2tg(+1)}, bank 8tg+g -> conflict-free.
// ---------------------------------------------------------------------------
#define KST 68
#define VST 68

__device__ __forceinline__ void attn_tile_mma(
    int qt, int h, int b,
    const float* __restrict__ Q, const float* __restrict__ Kg,
    const float* __restrict__ Vg, float* __restrict__ O,
    float (*KP)[KST], float (*Vs)[VST])
{
    const int tid  = threadIdx.x;
    const int lane = tid & 31;
    const int warp = tid >> 5;
    const int g    = lane >> 2;
    const int tg   = lane & 3;

    const size_t base = ((size_t)b * SS) * DD + (size_t)h * HD;
    const int qrow0 = qt * 64 + warp * 16 + g;
    const int qrow1 = qrow0 + 8;

    // Q fragments (scaled by 1/sqrt(hd), tf32)
    uint32_t qf[8][4];
    {
        const float* qp  = Q + base + (size_t)qrow0 * DD;
        const float* qp8 = qp + 8 * DD;
#pragma unroll
        for (int kf = 0; kf < 8; kf++) {
            qf[kf][0] = f2tf32(qp [kf * 8 + tg]     * 0.125f);
            qf[kf][1] = f2tf32(qp8[kf * 8 + tg]     * 0.125f);
            qf[kf][2] = f2tf32(qp [kf * 8 + tg + 4] * 0.125f);
            qf[kf][3] = f2tf32(qp8[kf * 8 + tg + 4] * 0.125f);
        }
    }

    float o[8][4];
#pragma unroll
    for (int nf = 0; nf < 8; nf++)
#pragma unroll
        for (int r = 0; r < 4; r++) o[nf][r] = 0.f;

    float m0 = -1e30f, m1 = -1e30f, l0 = 0.f, l1 = 0.f;
    const float slope = exp2f(-0.5f * (float)(h + 1));

    for (int kt = 0; kt <= qt; kt++) {
        __syncthreads();   // previous S/PV smem reads complete
        {
            const float* kb = Kg + base + (size_t)(kt * 64) * DD;
            const float* vb = Vg + base + (size_t)(kt * 64) * DD;
#pragma unroll
            for (int i = 0; i < 8; i++) {
                int n = i * 128 + tid;
                int r = n >> 4, c = (n & 15) << 2;
                float4 kv = *(const float4*)(kb + (size_t)r * DD + c);
                float4 vv = *(const float4*)(vb + (size_t)r * DD + c);
                KP[r][c + 0] = __uint_as_float(f2tf32(kv.x));
                KP[r][c + 1] = __uint_as_float(f2tf32(kv.y));
                KP[r][c + 2] = __uint_as_float(f2tf32(kv.z));
                KP[r][c + 3] = __uint_as_float(f2tf32(kv.w));
                Vs[r][c + 0] = __uint_as_float(f2tf32(vv.x));
                Vs[r][c + 1] = __uint_as_float(f2tf32(vv.y));
                Vs[r][c + 2] = __uint_as_float(f2tf32(vv.z));
                Vs[r][c + 3] = __uint_as_float(f2tf32(vv.w));
            }
        }
        __syncthreads();   // tiles ready

        // ---- S = Q K^T ----
        float s[8][4];
#pragma unroll
        for (int nf = 0; nf < 8; nf++)
#pragma unroll
            for (int r = 0; r < 4; r++) s[nf][r] = 0.f;

#pragma unroll
        for (int kf = 0; kf < 8; kf++) {
            const int kb = kf * 8;
#pragma unroll
            for (int nf = 0; nf < 8; nf++) {
                uint32_t b0 = __float_as_uint(KP[nf * 8 + g][kb + tg]);
                uint32_t b1 = __float_as_uint(KP[nf * 8 + g][kb + tg + 4]);
                asm volatile(
                    "mma.sync.aligned.m16n8k8.row.col.f32.tf32.tf32.f32 "
                    "{%0,%1,%2,%3}, {%4,%5,%6,%7}, {%8,%9}, {%0,%1,%2,%3};"
                    : "+f"(s[nf][0]), "+f"(s[nf][1]), "+f"(s[nf][2]), "+f"(s[nf][3])
                    : "r"(qf[kf][0]), "r"(qf[kf][1]), "r"(qf[kf][2]), "r"(qf[kf][3]),
                      "r"(b0), "r"(b1));
            }
        }

        // ---- ALiBi (column-only; row term is softmax-invariant) + mask ----
        const bool diag = (kt == qt);
        const int colb = kt * 64 + 2 * tg;
#pragma unroll
        for (int nf = 0; nf < 8; nf++) {
            const int c0 = colb + nf * 8;
            const float b0f = slope * (float)c0;
            const float b1f = slope * (float)(c0 + 1);
            s[nf][0] += b0f; s[nf][1] += b1f;
            s[nf][2] += b0f; s[nf][3] += b1f;
            if (diag) {
                if (c0     > qrow0) s[nf][0] = -1e30f;
                if (c0 + 1 > qrow0) s[nf][1] = -1e30f;
                if (c0     > qrow1) s[nf][2] = -1e30f;
                if (c0 + 1 > qrow1) s[nf][3] = -1e30f;
            }
        }

        // ---- online softmax ----
        float mx0 = -1e30f, mx1 = -1e30f;
#pragma unroll
        for (int nf = 0; nf < 8; nf++) {
            mx0 = fmaxf(mx0, fmaxf(s[nf][0], s[nf][1]));
            mx1 = fmaxf(mx1, fmaxf(s[nf][2], s[nf][3]));
        }
        mx0 = fmaxf(mx0, __shfl_xor_sync(0xffffffffu, mx0, 1));
        mx0 = fmaxf(mx0, __shfl_xor_sync(0xffffffffu, mx0, 2));
        mx1 = fmaxf(mx1, __shfl_xor_sync(0xffffffffu, mx1, 1));
        mx1 = fmaxf(mx1, __shfl_xor_sync(0xffffffffu, mx1, 2));

        const float mn0 = fmaxf(m0, mx0);
        const float mn1 = fmaxf(m1, mx1);
        const float a0 = __expf(m0 - mn0);
        const float a1 = __expf(m1 - mn1);
        m0 = mn0; m1 = mn1;

        float sum0 = 0.f, sum1 = 0.f;
#pragma unroll
        for (int nf = 0; nf < 8; nf++) {
            s[nf][0] = __expf(s[nf][0] - mn0);
            s[nf][1] = __expf(s[nf][1] - mn0);
            s[nf][2] = __expf(s[nf][2] - mn1);
            s[nf][3] = __expf(s[nf][3] - mn1);
            sum0 += s[nf][0] + s[nf][1];
            sum1 += s[nf][2] + s[nf][3];
        }
        sum0 += __shfl_xor_sync(0xffffffffu, sum0, 1);
        sum0 += __shfl_xor_sync(0xffffffffu, sum0, 2);
        sum1 += __shfl_xor_sync(0xffffffffu, sum1, 1);
        sum1 += __shfl_xor_sync(0xffffffffu, sum1, 2);
        l0 = l0 * a0 + sum0;
        l1 = l1 * a1 + sum1;

#pragma unroll
        for (int nf = 0; nf < 8; nf++) {
            o[nf][0] *= a0; o[nf][1] *= a0;
            o[nf][2] *= a1; o[nf][3] *= a1;
        }

        // ---- O += P V  (P = s regs, permuted-V B-frags; no smem for P) ----
#pragma unroll
        for (int kf = 0; kf < 8; kf++) {
            const uint32_t pa0 = __float_as_uint(s[kf][0]);
            const uint32_t pa1 = __float_as_uint(s[kf][2]);
            const uint32_t pa2 = __float_as_uint(s[kf][1]);
            const uint32_t pa3 = __float_as_uint(s[kf][3]);
            const int vr = kf * 8 + 2 * tg;
#pragma unroll
            for (int nf = 0; nf < 8; nf++) {
                uint32_t b0 = __float_as_uint(Vs[vr][nf * 8 + g]);
                uint32_t b1 = __float_as_uint(Vs[vr + 1][nf * 8 + g]);
                asm volatile(
                    "mma.sync.aligned.m16n8k8.row.col.f32.tf32.tf32.f32 "
                    "{%0,%1,%2,%3}, {%4,%5,%6,%7}, {%8,%9}, {%0,%1,%2,%3};"
                    : "+f"(o[nf][0]), "+f"(o[nf][1]), "+f"(o[nf][2]), "+f"(o[nf][3])
                    : "r"(pa0), "r"(pa1), "r"(pa2), "r"(pa3),
                      "r"(b0), "r"(b1));
            }
        }
    }

    // ---- normalize + write ----
    const float i0 = 1.f / l0;
    const float i1 = 1.f / l1;
    float* op0 = O + base + (size_t)qrow0 * DD;
    float* op1 = O + base + (size_t)qrow1 * DD;
#pragma unroll
    for (int nf = 0; nf < 8; nf++) {
        const int c = nf * 8 + 2 * tg;
        *(float2*)&op0[c] = make_float2(o[nf][0] * i0, o[nf][1] * i0);
        *(float2*)&op1[c] = make_float2(o[nf][2] * i1, o[nf][3] * i1);
    }
}

__global__ __launch_bounds__(128, 4) void attn_mma_kernel(
    const float* __restrict__ Q, const float* __restrict__ K,
    const float* __restrict__ V, float* __restrict__ O)
{
    __shared__ float KP[64][KST];
    __shared__ float Vs[64][VST];
    const int p = blockIdx.x;   // 0..15
    const int h = blockIdx.y;
    const int b = blockIdx.z;
    attn_tile_mma(p,      h, b, Q, K, V, O, KP, Vs);
    attn_tile_mma(31 - p, h, b, Q, K, V, O, KP, Vs);
}

// ---------------------------------------------------------------------------
extern "C" void kernel_launch(void* const* d_in, const int* in_sizes, int n_in,
                              void* d_out, int out_size)
{
    (void)in_sizes; (void)n_in; (void)out_size;
    const float* x   = (const float*)d_in[0];
    const float* q_w = (const float*)d_in[1];
    const float* q_b = (const float*)d_in[2];
    const float* k_w = (const float*)d_in[3];
    const float* k_b = (const float*)d_in[4];
    const float* v_w = (const float*)d_in[5];
    const float* v_b = (const float*)d_in[6];
    const float* o_w = (const float*)d_in[7];
    const float* o_b = (const float*)d_in[8];
    float* out = (float*)d_out;

    float *Qp, *Kp, *Vp, *Ap;
    cudaGetSymbolAddress((void**)&Qp, g_Q);
    cudaGetSymbolAddress((void**)&Kp, g_K);
    cudaGetSymbolAddress((void**)&Vp, g_V);
    cudaGetSymbolAddress((void**)&Ap, g_A);

    dim3 gg(DD / GBN, NTOK / GBM);   // (8, 32)
    gemm_tf32<<<gg, 256>>>(x, q_w, q_b, Qp, NTOK, DD, DD);
    gemm_tf32<<<gg, 256>>>(x, k_w, k_b, Kp, NTOK, DD, DD);
    gemm_tf32<<<gg, 256>>>(x, v_w, v_b, Vp, NTOK, DD, DD);

    dim3 ga(SS / 128, HH, BB);       // (16, 16, 2)
    attn_mma_kernel<<<ga, 128>>>(Qp, Kp, Vp, Ap);

    gemm_tf32<<<gg, 256>>>(Ap, o_w, o_b, out, NTOK, DD, DD);
}

// round 15
// speedup vs baseline: 2.3010x; 1.0411x over previous
#include <cuda_runtime.h>
#include <math.h>
#include <stdint.h>

#define BB 2
#define SS 2048
#define DD 1024
#define HH 16
#define HD 64
#define NTOK (BB * SS)

// Scratch (allocation-free rule: __device__ globals)
__device__ float g_Q[NTOK * DD];
__device__ float g_K[NTOK * DD];
__device__ float g_V[NTOK * DD];
__device__ float g_A[NTOK * DD];

__device__ __forceinline__ uint32_t f2tf32(float f) {
    uint32_t u;
    asm("cvt.rna.tf32.f32 %0, %1;" : "=r"(u) : "f"(f));
    return u;
}

// ---------------------------------------------------------------------------
// tf32 tensor-core GEMM:  C[M,N] = A[M,K] @ W[N,K]^T + bias[N]
// BM=128, BN=128, BK=32. 256 threads = 8 warps (4m x 2n), warp tile 32x64.
// ---------------------------------------------------------------------------
#define GBM 128
#define GBN 128
#define GBK 32

__global__ __launch_bounds__(256, 2) void gemm_tf32(
    const float* __restrict__ A, const float* __restrict__ W,
    const float* __restrict__ bias, float* __restrict__ C,
    int M, int N, int K)
{
    __shared__ float As[GBM][GBK + 4];
    __shared__ float Bs[GBN][GBK + 4];

    const int tid  = threadIdx.x;
    const int lane = tid & 31;
    const int warp = tid >> 5;
    const int g    = lane >> 2;
    const int tg   = lane & 3;
    const int wm   = warp >> 1;
    const int wn   = warp & 1;
    const int warpRow = wm * 32;
    const int warpCol = wn * 64;

    const int bm = blockIdx.y * GBM;
    const int bn = blockIdx.x * GBN;

    float acc[2][8][4];
#pragma unroll
    for (int i = 0; i < 2; i++)
#pragma unroll
        for (int j = 0; j < 8; j++)
#pragma unroll
            for (int r = 0; r < 4; r++) acc[i][j][r] = 0.f;

    const int f  = tid & 7;
    const int r0 = tid >> 3;

    const float* Ag = A + (size_t)(bm + r0) * K + f * 4;
    const float* Wg = W + (size_t)(bn + r0) * K + f * 4;

    float4 avp[4], wvp[4];
#pragma unroll
    for (int i = 0; i < 4; i++) {
        avp[i] = *(const float4*)(Ag + (size_t)(i * 32) * K);
        wvp[i] = *(const float4*)(Wg + (size_t)(i * 32) * K);
    }

    for (int k0 = 0; k0 < K; k0 += GBK) {
        __syncthreads();
#pragma unroll
        for (int i = 0; i < 4; i++) {
            int rr = r0 + i * 32;
            As[rr][f * 4 + 0] = __uint_as_float(f2tf32(avp[i].x));
            As[rr][f * 4 + 1] = __uint_as_float(f2tf32(avp[i].y));
            As[rr][f * 4 + 2] = __uint_as_float(f2tf32(avp[i].z));
            As[rr][f * 4 + 3] = __uint_as_float(f2tf32(avp[i].w));
            Bs[rr][f * 4 + 0] = __uint_as_float(f2tf32(wvp[i].x));
            Bs[rr][f * 4 + 1] = __uint_as_float(f2tf32(wvp[i].y));
            Bs[rr][f * 4 + 2] = __uint_as_float(f2tf32(wvp[i].z));
            Bs[rr][f * 4 + 3] = __uint_as_float(f2tf32(wvp[i].w));
        }
        __syncthreads();

        if (k0 + GBK < K) {
#pragma unroll
            for (int i = 0; i < 4; i++) {
                avp[i] = *(const float4*)(Ag + (size_t)(i * 32) * K + k0 + GBK);
                wvp[i] = *(const float4*)(Wg + (size_t)(i * 32) * K + k0 + GBK);
            }
        }

#pragma unroll
        for (int kk = 0; kk < 4; kk++) {
            const int kb = kk * 8;
            uint32_t a[2][4];
#pragma unroll
            for (int mf = 0; mf < 2; mf++) {
                const int r = warpRow + mf * 16 + g;
                a[mf][0] = __float_as_uint(As[r][kb + tg]);
                a[mf][1] = __float_as_uint(As[r + 8][kb + tg]);
                a[mf][2] = __float_as_uint(As[r][kb + tg + 4]);
                a[mf][3] = __float_as_uint(As[r + 8][kb + tg + 4]);
            }
            uint32_t b[8][2];
#pragma unroll
            for (int nf = 0; nf < 8; nf++) {
                const int c = warpCol + nf * 8 + g;
                b[nf][0] = __float_as_uint(Bs[c][kb + tg]);
                b[nf][1] = __float_as_uint(Bs[c][kb + tg + 4]);
            }
#pragma unroll
            for (int mf = 0; mf < 2; mf++)
#pragma unroll
                for (int nf = 0; nf < 8; nf++) {
                    asm volatile(
                        "mma.sync.aligned.m16n8k8.row.col.f32.tf32.tf32.f32 "
                        "{%0,%1,%2,%3}, {%4,%5,%6,%7}, {%8,%9}, {%0,%1,%2,%3};"
                        : "+f"(acc[mf][nf][0]), "+f"(acc[mf][nf][1]),
                          "+f"(acc[mf][nf][2]), "+f"(acc[mf][nf][3])
                        : "r"(a[mf][0]), "r"(a[mf][1]), "r"(a[mf][2]), "r"(a[mf][3]),
                          "r"(b[nf][0]), "r"(b[nf][1]));
                }
        }
    }

#pragma unroll
    for (int mf = 0; mf < 2; mf++) {
        const int r = bm + warpRow + mf * 16 + g;
#pragma unroll
        for (int nf = 0; nf < 8; nf++) {
            const int c = bn + warpCol + nf * 8 + 2 * tg;
            float2 bv = *(const float2*)&bias[c];
            float2 o0 = make_float2(acc[mf][nf][0] + bv.x, acc[mf][nf][1] + bv.y);
            float2 o1 = make_float2(acc[mf][nf][2] + bv.x, acc[mf][nf][3] + bv.y);
            *(float2*)&C[(size_t)r * N + c] = o0;
            *(float2*)&C[(size_t)(r + 8) * N + c] = o1;
        }
    }
}

// ---------------------------------------------------------------------------
// Tensor-core causal ALiBi flash attention (tf32 m16n8k8), P-in-registers,
// q-tile = 128 rows, warp tile M=32 (two m16 frags) => every K/V B-fragment
// LDS pair feeds two mma (halved LDS/mma vs M=16).
//
// Bank math: KST=VST=68 (68%32=4): K b-frags bank 4g+tg; V b-frag rows
// {8kf+2tg,+1} bank 8tg+g(+...) -> conflict-free.
// PV uses the S fragments directly as A-frags via the permuted V row map
// f = [0,2,4,6,1,3,5,7] (key-axis permutation, valid since P and V permute
// identically).
// ---------------------------------------------------------------------------
#define KST 68
#define VST 68
#define QTILE 128

__device__ __forceinline__ void attn_tile_mma(
    int qt, int h, int b,
    const float* __restrict__ Q, const float* __restrict__ Kg,
    const float* __restrict__ Vg, float* __restrict__ O,
    float (*KP)[KST], float (*Vs)[VST])
{
    const int tid  = threadIdx.x;
    const int lane = tid & 31;
    const int warp = tid >> 5;
    const int g    = lane >> 2;
    const int tg   = lane & 3;

    const size_t base = ((size_t)b * SS) * DD + (size_t)h * HD;
    const int qbase = qt * QTILE + warp * 32;
    const int warp_row_max = qbase + 31;

    // Q fragments for mf = 0,1 (scaled by 1/sqrt(hd), tf32)
    uint32_t qf[2][8][4];
#pragma unroll
    for (int mf = 0; mf < 2; mf++) {
        const float* qp  = Q + base + (size_t)(qbase + mf * 16 + g) * DD;
        const float* qp8 = qp + 8 * DD;
#pragma unroll
        for (int kf = 0; kf < 8; kf++) {
            qf[mf][kf][0] = f2tf32(qp [kf * 8 + tg]     * 0.125f);
            qf[mf][kf][1] = f2tf32(qp8[kf * 8 + tg]     * 0.125f);
            qf[mf][kf][2] = f2tf32(qp [kf * 8 + tg + 4] * 0.125f);
            qf[mf][kf][3] = f2tf32(qp8[kf * 8 + tg + 4] * 0.125f);
        }
    }

    float o[2][8][4];
#pragma unroll
    for (int mf = 0; mf < 2; mf++)
#pragma unroll
        for (int nf = 0; nf < 8; nf++)
#pragma unroll
            for (int r = 0; r < 4; r++) o[mf][nf][r] = 0.f;

    float mrow[2][2], lrow[2][2];
#pragma unroll
    for (int mf = 0; mf < 2; mf++) {
        mrow[mf][0] = -1e30f; mrow[mf][1] = -1e30f;
        lrow[mf][0] = 0.f;    lrow[mf][1] = 0.f;
    }
    const float slope = exp2f(-0.5f * (float)(h + 1));

    const int nkt = 2 * qt + 2;   // key tiles covering rows < (qt+1)*128

    for (int kt = 0; kt < nkt; kt++) {
        __syncthreads();
        {
            const float* kb = Kg + base + (size_t)(kt * 64) * DD;
            const float* vb = Vg + base + (size_t)(kt * 64) * DD;
#pragma unroll
            for (int i = 0; i < 8; i++) {
                int n = i * 128 + tid;
                int r = n >> 4, c = (n & 15) << 2;
                float4 kv = *(const float4*)(kb + (size_t)r * DD + c);
                float4 vv = *(const float4*)(vb + (size_t)r * DD + c);
                KP[r][c + 0] = __uint_as_float(f2tf32(kv.x));
                KP[r][c + 1] = __uint_as_float(f2tf32(kv.y));
                KP[r][c + 2] = __uint_as_float(f2tf32(kv.z));
                KP[r][c + 3] = __uint_as_float(f2tf32(kv.w));
                Vs[r][c + 0] = __uint_as_float(f2tf32(vv.x));
                Vs[r][c + 1] = __uint_as_float(f2tf32(vv.y));
                Vs[r][c + 2] = __uint_as_float(f2tf32(vv.z));
                Vs[r][c + 3] = __uint_as_float(f2tf32(vv.w));
            }
        }
        __syncthreads();

        // warp-uniform skip of fully-masked key tiles
        if (kt * 64 > warp_row_max) continue;

        // ---- S = Q K^T  (B-frag shared across mf) ----
        float s[2][8][4];
#pragma unroll
        for (int mf = 0; mf < 2; mf++)
#pragma unroll
            for (int nf = 0; nf < 8; nf++)
#pragma unroll
                for (int r = 0; r < 4; r++) s[mf][nf][r] = 0.f;

#pragma unroll
        for (int kf = 0; kf < 8; kf++) {
            const int kb = kf * 8;
#pragma unroll
            for (int nf = 0; nf < 8; nf++) {
                uint32_t b0 = __float_as_uint(KP[nf * 8 + g][kb + tg]);
                uint32_t b1 = __float_as_uint(KP[nf * 8 + g][kb + tg + 4]);
#pragma unroll
                for (int mf = 0; mf < 2; mf++) {
                    asm volatile(
                        "mma.sync.aligned.m16n8k8.row.col.f32.tf32.tf32.f32 "
                        "{%0,%1,%2,%3}, {%4,%5,%6,%7}, {%8,%9}, {%0,%1,%2,%3};"
                        : "+f"(s[mf][nf][0]), "+f"(s[mf][nf][1]),
                          "+f"(s[mf][nf][2]), "+f"(s[mf][nf][3])
                        : "r"(qf[mf][kf][0]), "r"(qf[mf][kf][1]),
                          "r"(qf[mf][kf][2]), "r"(qf[mf][kf][3]),
                          "r"(b0), "r"(b1));
                }
            }
        }

        // ---- ALiBi (column-only) + causal mask + online softmax + PV ----
        const bool diag = ((kt + 1) * 64 > qbase);   // tile may intersect diagonal
        const int colb = kt * 64 + 2 * tg;

#pragma unroll
        for (int mf = 0; mf < 2; mf++) {
            const int qrow0 = qbase + mf * 16 + g;
            const int qrow1 = qrow0 + 8;
#pragma unroll
            for (int nf = 0; nf < 8; nf++) {
                const int c0 = colb + nf * 8;
                const float b0f = slope * (float)c0;
                const float b1f = slope * (float)(c0 + 1);
                s[mf][nf][0] += b0f; s[mf][nf][1] += b1f;
                s[mf][nf][2] += b0f; s[mf][nf][3] += b1f;
                if (diag) {
                    if (c0     > qrow0) s[mf][nf][0] = -1e30f;
                    if (c0 + 1 > qrow0) s[mf][nf][1] = -1e30f;
                    if (c0     > qrow1) s[mf][nf][2] = -1e30f;
                    if (c0 + 1 > qrow1) s[mf][nf][3] = -1e30f;
                }
            }

            float mx0 = -1e30f, mx1 = -1e30f;
#pragma unroll
            for (int nf = 0; nf < 8; nf++) {
                mx0 = fmaxf(mx0, fmaxf(s[mf][nf][0], s[mf][nf][1]));
                mx1 = fmaxf(mx1, fmaxf(s[mf][nf][2], s[mf][nf][3]));
            }
            mx0 = fmaxf(mx0, __shfl_xor_sync(0xffffffffu, mx0, 1));
            mx0 = fmaxf(mx0, __shfl_xor_sync(0xffffffffu, mx0, 2));
            mx1 = fmaxf(mx1, __shfl_xor_sync(0xffffffffu, mx1, 1));
            mx1 = fmaxf(mx1, __shfl_xor_sync(0xffffffffu, mx1, 2));

            const float mn0 = fmaxf(mrow[mf][0], mx0);
            const float mn1 = fmaxf(mrow[mf][1], mx1);
            const float a0 = __expf(mrow[mf][0] - mn0);
            const float a1 = __expf(mrow[mf][1] - mn1);
            mrow[mf][0] = mn0; mrow[mf][1] = mn1;

            float sum0 = 0.f, sum1 = 0.f;
#pragma unroll
            for (int nf = 0; nf < 8; nf++) {
                s[mf][nf][0] = __expf(s[mf][nf][0] - mn0);
                s[mf][nf][1] = __expf(s[mf][nf][1] - mn0);
                s[mf][nf][2] = __expf(s[mf][nf][2] - mn1);
                s[mf][nf][3] = __expf(s[mf][nf][3] - mn1);
                sum0 += s[mf][nf][0] + s[mf][nf][1];
                sum1 += s[mf][nf][2] + s[mf][nf][3];
            }
            sum0 += __shfl_xor_sync(0xffffffffu, sum0, 1);
            sum0 += __shfl_xor_sync(0xffffffffu, sum0, 2);
            sum1 += __shfl_xor_sync(0xffffffffu, sum1, 1);
            sum1 += __shfl_xor_sync(0xffffffffu, sum1, 2);
            lrow[mf][0] = lrow[mf][0] * a0 + sum0;
            lrow[mf][1] = lrow[mf][1] * a1 + sum1;

#pragma unroll
            for (int nf = 0; nf < 8; nf++) {
                o[mf][nf][0] *= a0; o[mf][nf][1] *= a0;
                o[mf][nf][2] *= a1; o[mf][nf][3] *= a1;
            }
        }

        // ---- O += P V  (B-frag shared across mf) ----
#pragma unroll
        for (int kf = 0; kf < 8; kf++) {
            const int vr = kf * 8 + 2 * tg;
#pragma unroll
            for (int nf = 0; nf < 8; nf++) {
                uint32_t b0 = __float_as_uint(Vs[vr][nf * 8 + g]);
                uint32_t b1 = __float_as_uint(Vs[vr + 1][nf * 8 + g]);
#pragma unroll
                for (int mf = 0; mf < 2; mf++) {
                    asm volatile(
                        "mma.sync.aligned.m16n8k8.row.col.f32.tf32.tf32.f32 "
                        "{%0,%1,%2,%3}, {%4,%5,%6,%7}, {%8,%9}, {%0,%1,%2,%3};"
                        : "+f"(o[mf][nf][0]), "+f"(o[mf][nf][1]),
                          "+f"(o[mf][nf][2]), "+f"(o[mf][nf][3])
                        : "r"(__float_as_uint(s[mf][kf][0])),
                          "r"(__float_as_uint(s[mf][kf][2])),
                          "r"(__float_as_uint(s[mf][kf][1])),
                          "r"(__float_as_uint(s[mf][kf][3])),
                          "r"(b0), "r"(b1));
                }
            }
        }
    }

    // ---- normalize + write ----
#pragma unroll
    for (int mf = 0; mf < 2; mf++) {
        const float i0 = 1.f / lrow[mf][0];
        const float i1 = 1.f / lrow[mf][1];
        float* op0 = O + base + (size_t)(qbase + mf * 16 + g) * DD;
        float* op1 = op0 + 8 * DD;
#pragma unroll
        for (int nf = 0; nf < 8; nf++) {
            const int c = nf * 8 + 2 * tg;
            *(float2*)&op0[c] = make_float2(o[mf][nf][0] * i0, o[mf][nf][1] * i0);
            *(float2*)&op1[c] = make_float2(o[mf][nf][2] * i1, o[mf][nf][3] * i1);
        }
    }
}

__global__ __launch_bounds__(128, 2) void attn_mma_kernel(
    const float* __restrict__ Q, const float* __restrict__ K,
    const float* __restrict__ V, float* __restrict__ O)
{
    __shared__ float KP[64][KST];
    __shared__ float Vs[64][VST];
    const int p = blockIdx.x;   // 0..7
    const int h = blockIdx.y;
    const int b = blockIdx.z;
    attn_tile_mma(p,      h, b, Q, K, V, O, KP, Vs);
    attn_tile_mma(15 - p, h, b, Q, K, V, O, KP, Vs);
}

// ---------------------------------------------------------------------------
extern "C" void kernel_launch(void* const* d_in, const int* in_sizes, int n_in,
                              void* d_out, int out_size)
{
    (void)in_sizes; (void)n_in; (void)out_size;
    const float* x   = (const float*)d_in[0];
    const float* q_w = (const float*)d_in[1];
    const float* q_b = (const float*)d_in[2];
    const float* k_w = (const float*)d_in[3];
    const float* k_b = (const float*)d_in[4];
    const float* v_w = (const float*)d_in[5];
    const float* v_b = (const float*)d_in[6];
    const float* o_w = (const float*)d_in[7];
    const float* o_b = (const float*)d_in[8];
    float* out = (float*)d_out;

    float *Qp, *Kp, *Vp, *Ap;
    cudaGetSymbolAddress((void**)&Qp, g_Q);
    cudaGetSymbolAddress((void**)&Kp, g_K);
    cudaGetSymbolAddress((void**)&Vp, g_V);
    cudaGetSymbolAddress((void**)&Ap, g_A);

    dim3 gg(DD / GBN, NTOK / GBM);   // (8, 32)
    gemm_tf32<<<gg, 256>>>(x, q_w, q_b, Qp, NTOK, DD, DD);
    gemm_tf32<<<gg, 256>>>(x, k_w, k_b, Kp, NTOK, DD, DD);
    gemm_tf32<<<gg, 256>>>(x, v_w, v_b, Vp, NTOK, DD, DD);

    dim3 ga(SS / (2 * QTILE), HH, BB);   // (8, 16, 2)
    attn_mma_kernel<<<ga, 128>>>(Qp, Kp, Vp, Ap);

    gemm_tf32<<<gg, 256>>>(Ap, o_w, o_b, out, NTOK, DD, DD);
}

// round 16
// speedup vs baseline: 2.3105x; 1.0041x over previous
#include <cuda_runtime.h>
#include <math.h>
#include <stdint.h>

#define BB 2
#define SS 2048
#define DD 1024
#define HH 16
#define HD 64
#define NTOK (BB * SS)

// Scratch (allocation-free rule: __device__ globals)
__device__ float g_Q[NTOK * DD];
__device__ float g_K[NTOK * DD];
__device__ float g_V[NTOK * DD];
__device__ float g_A[NTOK * DD];

__device__ __forceinline__ uint32_t f2tf32(float f) {
    uint32_t u;
    asm("cvt.rna.tf32.f32 %0, %1;" : "=r"(u) : "f"(f));
    return u;
}

// ---------------------------------------------------------------------------
// tf32 tensor-core GEMM:  C[M,N] = A[M,K] @ W[N,K]^T + bias[N]
// BM=128, BN=128, BK=32. 256 threads = 8 warps (4m x 2n), warp tile 32x64.
// ---------------------------------------------------------------------------
#define GBM 128
#define GBN 128
#define GBK 32

__global__ __launch_bounds__(256, 2) void gemm_tf32(
    const float* __restrict__ A, const float* __restrict__ W,
    const float* __restrict__ bias, float* __restrict__ C,
    int M, int N, int K)
{
    __shared__ float As[GBM][GBK + 4];
    __shared__ float Bs[GBN][GBK + 4];

    const int tid  = threadIdx.x;
    const int lane = tid & 31;
    const int warp = tid >> 5;
    const int g    = lane >> 2;
    const int tg   = lane & 3;
    const int wm   = warp >> 1;
    const int wn   = warp & 1;
    const int warpRow = wm * 32;
    const int warpCol = wn * 64;

    const int bm = blockIdx.y * GBM;
    const int bn = blockIdx.x * GBN;

    float acc[2][8][4];
#pragma unroll
    for (int i = 0; i < 2; i++)
#pragma unroll
        for (int j = 0; j < 8; j++)
#pragma unroll
            for (int r = 0; r < 4; r++) acc[i][j][r] = 0.f;

    const int f  = tid & 7;
    const int r0 = tid >> 3;

    const float* Ag = A + (size_t)(bm + r0) * K + f * 4;
    const float* Wg = W + (size_t)(bn + r0) * K + f * 4;

    float4 avp[4], wvp[4];
#pragma unroll
    for (int i = 0; i < 4; i++) {
        avp[i] = *(const float4*)(Ag + (size_t)(i * 32) * K);
        wvp[i] = *(const float4*)(Wg + (size_t)(i * 32) * K);
    }

    for (int k0 = 0; k0 < K; k0 += GBK) {
        __syncthreads();
#pragma unroll
        for (int i = 0; i < 4; i++) {
            int rr = r0 + i * 32;
            As[rr][f * 4 + 0] = __uint_as_float(f2tf32(avp[i].x));
            As[rr][f * 4 + 1] = __uint_as_float(f2tf32(avp[i].y));
            As[rr][f * 4 + 2] = __uint_as_float(f2tf32(avp[i].z));
            As[rr][f * 4 + 3] = __uint_as_float(f2tf32(avp[i].w));
            Bs[rr][f * 4 + 0] = __uint_as_float(f2tf32(wvp[i].x));
            Bs[rr][f * 4 + 1] = __uint_as_float(f2tf32(wvp[i].y));
            Bs[rr][f * 4 + 2] = __uint_as_float(f2tf32(wvp[i].z));
            Bs[rr][f * 4 + 3] = __uint_as_float(f2tf32(wvp[i].w));
        }
        __syncthreads();

        if (k0 + GBK < K) {
#pragma unroll
            for (int i = 0; i < 4; i++) {
                avp[i] = *(const float4*)(Ag + (size_t)(i * 32) * K + k0 + GBK);
                wvp[i] = *(const float4*)(Wg + (size_t)(i * 32) * K + k0 + GBK);
            }
        }

#pragma unroll
        for (int kk = 0; kk < 4; kk++) {
            const int kb = kk * 8;
            uint32_t a[2][4];
#pragma unroll
            for (int mf = 0; mf < 2; mf++) {
                const int r = warpRow + mf * 16 + g;
                a[mf][0] = __float_as_uint(As[r][kb + tg]);
                a[mf][1] = __float_as_uint(As[r + 8][kb + tg]);
                a[mf][2] = __float_as_uint(As[r][kb + tg + 4]);
                a[mf][3] = __float_as_uint(As[r + 8][kb + tg + 4]);
            }
            uint32_t b[8][2];
#pragma unroll
            for (int nf = 0; nf < 8; nf++) {
                const int c = warpCol + nf * 8 + g;
                b[nf][0] = __float_as_uint(Bs[c][kb + tg]);
                b[nf][1] = __float_as_uint(Bs[c][kb + tg + 4]);
            }
#pragma unroll
            for (int mf = 0; mf < 2; mf++)
#pragma unroll
                for (int nf = 0; nf < 8; nf++) {
                    asm volatile(
                        "mma.sync.aligned.m16n8k8.row.col.f32.tf32.tf32.f32 "
                        "{%0,%1,%2,%3}, {%4,%5,%6,%7}, {%8,%9}, {%0,%1,%2,%3};"
                        : "+f"(acc[mf][nf][0]), "+f"(acc[mf][nf][1]),
                          "+f"(acc[mf][nf][2]), "+f"(acc[mf][nf][3])
                        : "r"(a[mf][0]), "r"(a[mf][1]), "r"(a[mf][2]), "r"(a[mf][3]),
                          "r"(b[nf][0]), "r"(b[nf][1]));
                }
        }
    }

#pragma unroll
    for (int mf = 0; mf < 2; mf++) {
        const int r = bm + warpRow + mf * 16 + g;
#pragma unroll
        for (int nf = 0; nf < 8; nf++) {
            const int c = bn + warpCol + nf * 8 + 2 * tg;
            float2 bv = *(const float2*)&bias[c];
            float2 o0 = make_float2(acc[mf][nf][0] + bv.x, acc[mf][nf][1] + bv.y);
            float2 o1 = make_float2(acc[mf][nf][2] + bv.x, acc[mf][nf][3] + bv.y);
            *(float2*)&C[(size_t)r * N + c] = o0;
            *(float2*)&C[(size_t)(r + 8) * N + c] = o1;
        }
    }
}

// ---------------------------------------------------------------------------
// Tensor-core causal ALiBi flash attention (tf32 m16n8k8), P-in-registers,
// q-tile 128, warp tile M=32, cp.async double-buffered K/V tiles.
//
// K/V are copied raw fp32 -> smem via cp.async.cg (16B) into a 2-stage ring;
// the mma interprets the bits as tf32 (HW truncation), same as the P operand.
// Bank math unchanged: KST=VST=68 -> conflict-free B-fragment reads.
// ---------------------------------------------------------------------------
#define KST 68
#define VST 68
#define QTILE 128
#define STAGE_F (64 * KST + 64 * VST)          // floats per stage
#define ATTN_SMEM_BYTES (2 * STAGE_F * 4)      // 69632 B

__device__ __forceinline__ void cp16(uint32_t dst, const void* src) {
    asm volatile("cp.async.cg.shared.global [%0], [%1], 16;" :: "r"(dst), "l"(src));
}

__device__ __forceinline__ void load_tile_async(
    float* stage, const float* kb, const float* vb, int tid)
{
    float* Kb = stage;
    float* Vb = stage + 64 * KST;
#pragma unroll
    for (int i = 0; i < 8; i++) {
        int n = i * 128 + tid;
        int r = n >> 4, c = (n & 15) << 2;
        const float* ks = kb + (size_t)r * DD + c;
        const float* vs = vb + (size_t)r * DD + c;
        cp16((uint32_t)__cvta_generic_to_shared(&Kb[r * KST + c]), ks);
        cp16((uint32_t)__cvta_generic_to_shared(&Vb[r * VST + c]), vs);
    }
    asm volatile("cp.async.commit_group;");
}

__device__ __forceinline__ void attn_tile_mma(
    int qt, int h, int b,
    const float* __restrict__ Q, const float* __restrict__ Kg,
    const float* __restrict__ Vg, float* __restrict__ O,
    float* sm)
{
    const int tid  = threadIdx.x;
    const int lane = tid & 31;
    const int warp = tid >> 5;
    const int g    = lane >> 2;
    const int tg   = lane & 3;

    const size_t base = ((size_t)b * SS) * DD + (size_t)h * HD;
    const int qbase = qt * QTILE + warp * 32;
    const int warp_row_max = qbase + 31;

    // Q fragments for mf = 0,1 (scaled by 1/sqrt(hd), tf32 rna)
    uint32_t qf[2][8][4];
#pragma unroll
    for (int mf = 0; mf < 2; mf++) {
        const float* qp  = Q + base + (size_t)(qbase + mf * 16 + g) * DD;
        const float* qp8 = qp + 8 * DD;
#pragma unroll
        for (int kf = 0; kf < 8; kf++) {
            qf[mf][kf][0] = f2tf32(qp [kf * 8 + tg]     * 0.125f);
            qf[mf][kf][1] = f2tf32(qp8[kf * 8 + tg]     * 0.125f);
            qf[mf][kf][2] = f2tf32(qp [kf * 8 + tg + 4] * 0.125f);
            qf[mf][kf][3] = f2tf32(qp8[kf * 8 + tg + 4] * 0.125f);
        }
    }

    float o[2][8][4];
#pragma unroll
    for (int mf = 0; mf < 2; mf++)
#pragma unroll
        for (int nf = 0; nf < 8; nf++)
#pragma unroll
            for (int r = 0; r < 4; r++) o[mf][nf][r] = 0.f;

    float mrow[2][2], lrow[2][2];
#pragma unroll
    for (int mf = 0; mf < 2; mf++) {
        mrow[mf][0] = -1e30f; mrow[mf][1] = -1e30f;
        lrow[mf][0] = 0.f;    lrow[mf][1] = 0.f;
    }
    const float slope = exp2f(-0.5f * (float)(h + 1));

    const int nkt = 2 * qt + 2;   // key tiles covering rows < (qt+1)*128

    // prologue: prefetch tile 0 into stage 0
    load_tile_async(sm, Kg + base, Vg + base, tid);

    for (int kt = 0; kt < nkt; kt++) {
        if (kt + 1 < nkt) {
            load_tile_async(sm + ((kt + 1) & 1) * STAGE_F,
                            Kg + base + (size_t)((kt + 1) * 64) * DD,
                            Vg + base + (size_t)((kt + 1) * 64) * DD, tid);
            asm volatile("cp.async.wait_group 1;");
        } else {
            asm volatile("cp.async.wait_group 0;");
        }
        __syncthreads();   // tile kt visible to all threads

        float (*KP)[KST] = (float (*)[KST])(sm + (kt & 1) * STAGE_F);
        float (*Vs)[VST] = (float (*)[VST])(sm + (kt & 1) * STAGE_F + 64 * KST);

        // warp-uniform skip of fully-masked key tiles (barriers stay uniform)
        if (kt * 64 <= warp_row_max) {
            // ---- S = Q K^T  (B-frag shared across mf) ----
            float s[2][8][4];
#pragma unroll
            for (int mf = 0; mf < 2; mf++)
#pragma unroll
                for (int nf = 0; nf < 8; nf++)
#pragma unroll
                    for (int r = 0; r < 4; r++) s[mf][nf][r] = 0.f;

#pragma unroll
            for (int kf = 0; kf < 8; kf++) {
                const int kb = kf * 8;
#pragma unroll
                for (int nf = 0; nf < 8; nf++) {
                    uint32_t b0 = __float_as_uint(KP[nf * 8 + g][kb + tg]);
                    uint32_t b1 = __float_as_uint(KP[nf * 8 + g][kb + tg + 4]);
#pragma unroll
                    for (int mf = 0; mf < 2; mf++) {
                        asm volatile(
                            "mma.sync.aligned.m16n8k8.row.col.f32.tf32.tf32.f32 "
                            "{%0,%1,%2,%3}, {%4,%5,%6,%7}, {%8,%9}, {%0,%1,%2,%3};"
                            : "+f"(s[mf][nf][0]), "+f"(s[mf][nf][1]),
                              "+f"(s[mf][nf][2]), "+f"(s[mf][nf][3])
                            : "r"(qf[mf][kf][0]), "r"(qf[mf][kf][1]),
                              "r"(qf[mf][kf][2]), "r"(qf[mf][kf][3]),
                              "r"(b0), "r"(b1));
                    }
                }
            }

            // ---- ALiBi (column-only) + causal mask + online softmax ----
            const bool diag = ((kt + 1) * 64 > qbase);
            const int colb = kt * 64 + 2 * tg;

#pragma unroll
            for (int mf = 0; mf < 2; mf++) {
                const int qrow0 = qbase + mf * 16 + g;
                const int qrow1 = qrow0 + 8;
#pragma unroll
                for (int nf = 0; nf < 8; nf++) {
                    const int c0 = colb + nf * 8;
                    const float b0f = slope * (float)c0;
                    const float b1f = slope * (float)(c0 + 1);
                    s[mf][nf][0] += b0f; s[mf][nf][1] += b1f;
                    s[mf][nf][2] += b0f; s[mf][nf][3] += b1f;
                    if (diag) {
                        if (c0     > qrow0) s[mf][nf][0] = -1e30f;
                        if (c0 + 1 > qrow0) s[mf][nf][1] = -1e30f;
                        if (c0     > qrow1) s[mf][nf][2] = -1e30f;
                        if (c0 + 1 > qrow1) s[mf][nf][3] = -1e30f;
                    }
                }

                float mx0 = -1e30f, mx1 = -1e30f;
#pragma unroll
                for (int nf = 0; nf < 8; nf++) {
                    mx0 = fmaxf(mx0, fmaxf(s[mf][nf][0], s[mf][nf][1]));
                    mx1 = fmaxf(mx1, fmaxf(s[mf][nf][2], s[mf][nf][3]));
                }
                mx0 = fmaxf(mx0, __shfl_xor_sync(0xffffffffu, mx0, 1));
                mx0 = fmaxf(mx0, __shfl_xor_sync(0xffffffffu, mx0, 2));
                mx1 = fmaxf(mx1, __shfl_xor_sync(0xffffffffu, mx1, 1));
                mx1 = fmaxf(mx1, __shfl_xor_sync(0xffffffffu, mx1, 2));

                const float mn0 = fmaxf(mrow[mf][0], mx0);
                const float mn1 = fmaxf(mrow[mf][1], mx1);
                const float a0 = __expf(mrow[mf][0] - mn0);
                const float a1 = __expf(mrow[mf][1] - mn1);
                mrow[mf][0] = mn0; mrow[mf][1] = mn1;

                float sum0 = 0.f, sum1 = 0.f;
#pragma unroll
                for (int nf = 0; nf < 8; nf++) {
                    s[mf][nf][0] = __expf(s[mf][nf][0] - mn0);
                    s[mf][nf][1] = __expf(s[mf][nf][1] - mn0);
                    s[mf][nf][2] = __expf(s[mf][nf][2] - mn1);
                    s[mf][nf][3] = __expf(s[mf][nf][3] - mn1);
                    sum0 += s[mf][nf][0] + s[mf][nf][1];
                    sum1 += s[mf][nf][2] + s[mf][nf][3];
                }
                sum0 += __shfl_xor_sync(0xffffffffu, sum0, 1);
                sum0 += __shfl_xor_sync(0xffffffffu, sum0, 2);
                sum1 += __shfl_xor_sync(0xffffffffu, sum1, 1);
                sum1 += __shfl_xor_sync(0xffffffffu, sum1, 2);
                lrow[mf][0] = lrow[mf][0] * a0 + sum0;
                lrow[mf][1] = lrow[mf][1] * a1 + sum1;

#pragma unroll
                for (int nf = 0; nf < 8; nf++) {
                    o[mf][nf][0] *= a0; o[mf][nf][1] *= a0;
                    o[mf][nf][2] *= a1; o[mf][nf][3] *= a1;
                }
            }

            // ---- O += P V  (permuted-V B-frags, P = s regs) ----
#pragma unroll
            for (int kf = 0; kf < 8; kf++) {
                const int vr = kf * 8 + 2 * tg;
#pragma unroll
                for (int nf = 0; nf < 8; nf++) {
                    uint32_t b0 = __float_as_uint(Vs[vr][nf * 8 + g]);
                    uint32_t b1 = __float_as_uint(Vs[vr + 1][nf * 8 + g]);
#pragma unroll
                    for (int mf = 0; mf < 2; mf++) {
                        asm volatile(
                            "mma.sync.aligned.m16n8k8.row.col.f32.tf32.tf32.f32 "
                            "{%0,%1,%2,%3}, {%4,%5,%6,%7}, {%8,%9}, {%0,%1,%2,%3};"
                            : "+f"(o[mf][nf][0]), "+f"(o[mf][nf][1]),
                              "+f"(o[mf][nf][2]), "+f"(o[mf][nf][3])
                            : "r"(__float_as_uint(s[mf][kf][0])),
                              "r"(__float_as_uint(s[mf][kf][2])),
                              "r"(__float_as_uint(s[mf][kf][1])),
                              "r"(__float_as_uint(s[mf][kf][3])),
                              "r"(b0), "r"(b1));
                    }
                }
            }
        }

        __syncthreads();   // all reads of stage (kt&1) done before reuse
    }

    // ---- normalize + write ----
#pragma unroll
    for (int mf = 0; mf < 2; mf++) {
        const float i0 = 1.f / lrow[mf][0];
        const float i1 = 1.f / lrow[mf][1];
        float* op0 = O + base + (size_t)(qbase + mf * 16 + g) * DD;
        float* op1 = op0 + 8 * DD;
#pragma unroll
        for (int nf = 0; nf < 8; nf++) {
            const int c = nf * 8 + 2 * tg;
            *(float2*)&op0[c] = make_float2(o[mf][nf][0] * i0, o[mf][nf][1] * i0);
            *(float2*)&op1[c] = make_float2(o[mf][nf][2] * i1, o[mf][nf][3] * i1);
        }
    }
}

__global__ __launch_bounds__(128, 2) void attn_mma_kernel(
    const float* __restrict__ Q, const float* __restrict__ K,
    const float* __restrict__ V, float* __restrict__ O)
{
    extern __shared__ float sm[];
    const int p = blockIdx.x;   // 0..7
    const int h = blockIdx.y;
    const int b = blockIdx.z;
    attn_tile_mma(p,      h, b, Q, K, V, O, sm);
    attn_tile_mma(15 - p, h, b, Q, K, V, O, sm);
}

// ---------------------------------------------------------------------------
extern "C" void kernel_launch(void* const* d_in, const int* in_sizes, int n_in,
                              void* d_out, int out_size)
{
    (void)in_sizes; (void)n_in; (void)out_size;
    const float* x   = (const float*)d_in[0];
    const float* q_w = (const float*)d_in[1];
    const float* q_b = (const float*)d_in[2];
    const float* k_w = (const float*)d_in[3];
    const float* k_b = (const float*)d_in[4];
    const float* v_w = (const float*)d_in[5];
    const float* v_b = (const float*)d_in[6];
    const float* o_w = (const float*)d_in[7];
    const float* o_b = (const float*)d_in[8];
    float* out = (float*)d_out;

    float *Qp, *Kp, *Vp, *Ap;
    cudaGetSymbolAddress((void**)&Qp, g_Q);
    cudaGetSymbolAddress((void**)&Kp, g_K);
    cudaGetSymbolAddress((void**)&Vp, g_V);
    cudaGetSymbolAddress((void**)&Ap, g_A);

    cudaFuncSetAttribute(attn_mma_kernel,
                         cudaFuncAttributeMaxDynamicSharedMemorySize,
                         ATTN_SMEM_BYTES);

    dim3 gg(DD / GBN, NTOK / GBM);   // (8, 32)
    gemm_tf32<<<gg, 256>>>(x, q_w, q_b, Qp, NTOK, DD, DD);
    gemm_tf32<<<gg, 256>>>(x, k_w, k_b, Kp, NTOK, DD, DD);
    gemm_tf32<<<gg, 256>>>(x, v_w, v_b, Vp, NTOK, DD, DD);

    dim3 ga(SS / (2 * QTILE), HH, BB);   // (8, 16, 2)
    attn_mma_kernel<<<ga, 128, ATTN_SMEM_BYTES>>>(Qp, Kp, Vp, Ap);

    gemm_tf32<<<gg, 256>>>(Ap, o_w, o_b, out, NTOK, DD, DD);
}